// round 9
// baseline (speedup 1.0000x reference)
#include <cuda_runtime.h>
#include <cuda_fp16.h>
#include <math.h>
#include <stdint.h>

typedef unsigned long long ull;

#define B_TOT 8192
#define T_TOT 128
#define NNODE 5
#define FML   64
#define F0    256
#define DIN   130
#define KFEAT 325
#define TILE_B 64
#define NTHR   256
#define KT     16
#define LDF    336

#define SM_M   128        // batch rows per step CTA (1 CTA/SM, halves per-SM B traffic)
#define STHR   512        // 16 warps: 4 M-bands x 4 N-cols
#define LDA    264        // A row pitch in halves (528B)
#define LDB    264        // B chunk row pitch (L1/L2)
#define LDB3   72         // B chunk row pitch (L3)
#define K1     144        // padded K of layer1
#define NCHUNK 33         // flat chunks: L1 9 (k16) + L2 16 (k16) + L3 8 (k32)

__constant__ int c_par[NNODE][2] = {{3,4},{0,4},{0,1},{1,2},{2,3}};

// ---------------- device scratch ----------------
__device__ float g_state2[2][NNODE][B_TOT][FML];
__device__ float g_h[(size_t)B_TOT*F0];
__device__ float g_psum[(B_TOT/TILE_B)*F0];
__device__ float g_psq [(B_TOT/TILE_B)*F0];
__device__ float g_scale[F0], g_shift[F0];
// fp16-split weights, chunked [nd][chunk][16][pitch]
__device__ __half g_W1h[5*9*16*LDB],  g_W1l[5*9*16*LDB];
__device__ __half g_W2h[5*16*16*LDB], g_W2l[5*16*16*LDB];
__device__ __half g_W3h[5*16*16*LDB3],g_W3l[5*16*16*LDB3];

// ---------------- f32x2 helpers (final head GEMM) ----------------
__device__ __forceinline__ ull fma2(ull a, ull b, ull c) {
    ull d; asm("fma.rn.f32x2 %0, %1, %2, %3;" : "=l"(d) : "l"(a), "l"(b), "l"(c)); return d;
}
__device__ __forceinline__ ull pack2(float x, float y) {
    ull d; asm("mov.b64 %0, {%1, %2};" : "=l"(d) : "f"(x), "f"(y)); return d;
}
__device__ __forceinline__ float2 unpack2(ull v) {
    float2 r; asm("mov.b64 {%0, %1}, %2;" : "=f"(r.x), "=f"(r.y) : "l"(v)); return r;
}

// ---------------- tensor-core primitives (baseline PTX, sm_80+) ----------------
__device__ __forceinline__ uint32_t smem_to_u32(const void* p) {
    uint32_t a; asm("{ .reg .u64 t; cvta.to.shared.u64 t, %1; cvt.u32.u64 %0, t; }" : "=r"(a) : "l"(p)); return a;
}
__device__ __forceinline__ void ldsm4(uint32_t a, uint32_t* r) {
    asm volatile("ldmatrix.sync.aligned.m8n8.x4.shared.b16 {%0,%1,%2,%3}, [%4];"
        : "=r"(r[0]), "=r"(r[1]), "=r"(r[2]), "=r"(r[3]) : "r"(a));
}
__device__ __forceinline__ void ldsm4t(uint32_t a, uint32_t* r) {
    asm volatile("ldmatrix.sync.aligned.m8n8.x4.trans.shared.b16 {%0,%1,%2,%3}, [%4];"
        : "=r"(r[0]), "=r"(r[1]), "=r"(r[2]), "=r"(r[3]) : "r"(a));
}
__device__ __forceinline__ void mma16816(float* c, const uint32_t* a, uint32_t b0, uint32_t b1) {
    asm volatile("mma.sync.aligned.m16n8k16.row.col.f32.f16.f16.f32 "
        "{%0,%1,%2,%3}, {%4,%5,%6,%7}, {%8,%9}, {%0,%1,%2,%3};"
        : "+f"(c[0]), "+f"(c[1]), "+f"(c[2]), "+f"(c[3])
        : "r"(a[0]), "r"(a[1]), "r"(a[2]), "r"(a[3]), "r"(b0), "r"(b1));
}
__device__ __forceinline__ void cp16(uint32_t dst, const void* src) {
    asm volatile("cp.async.cg.shared.global [%0], [%1], 16;" :: "r"(dst), "l"(src));
}
#define CP_COMMIT() asm volatile("cp.async.commit_group;" ::: "memory")
#define CP_WAIT3()  asm volatile("cp.async.wait_group 3;" ::: "memory")

// smem byte offsets (SM_M = 128)
#define OFF_AH   0
#define OFF_AL   67584                 // 128*264*2
#define OFF_B    135168                // 4 buffers x (Bh 8448 | Bl 8448)
#define BUF_STRIDE 16896
#define OFF_BIAS 202752                // b1 (1024B) | b2 (1024B) | b3 (256B)
#define STEP_SMEM (202752 + 2304)

// ---------------- weight prep: transpose-to-chunks + fp16 split ----------------
__global__ void prep_kernel(const float* __restrict__ W1, const float* __restrict__ W2,
                            const float* __restrict__ W3) {
    int i0 = blockIdx.x*blockDim.x + threadIdx.x, gs = gridDim.x*blockDim.x;
    for (int i = i0; i < 5*9*16*LDB; i += gs) {        // W1: [nd][9][16][264]
        int nd = i/(9*16*LDB), r = i%(9*16*LDB);
        int kc = r/(16*LDB), q = r%(16*LDB), kr = q/LDB, n = q%LDB;
        int k = kc*16 + kr;
        float v = (k < DIN && n < F0) ? W1[((size_t)nd*DIN + k)*F0 + n] : 0.f;
        __half h = __float2half_rn(v);
        g_W1h[i] = h; g_W1l[i] = __float2half_rn(v - __half2float(h));
    }
    for (int i = i0; i < 5*16*16*LDB; i += gs) {       // W2: [nd][16][16][264]
        int nd = i/(16*16*LDB), r = i%(16*16*LDB);
        int kc = r/(16*LDB), q = r%(16*LDB), kr = q/LDB, n = q%LDB;
        int k = kc*16 + kr;
        float v = (n < F0) ? W2[((size_t)nd*F0 + k)*F0 + n] : 0.f;
        __half h = __float2half_rn(v);
        g_W2h[i] = h; g_W2l[i] = __float2half_rn(v - __half2float(h));
    }
    for (int i = i0; i < 5*16*16*LDB3; i += gs) {      // W3: [nd][16][16][72]
        int nd = i/(16*16*LDB3), r = i%(16*16*LDB3);
        int kc = r/(16*LDB3), q = r%(16*LDB3), kr = q/LDB3, n = q%LDB3;
        int k = kc*16 + kr;
        float v = (n < FML) ? W3[((size_t)nd*F0 + k)*FML + n] : 0.f;
        __half h = __float2half_rn(v);
        g_W3h[i] = h; g_W3l[i] = __float2half_rn(v - __half2float(h));
    }
}

// B chunk loader: linear 16B copies. n16 = 16B units per (hi|lo) part.
__device__ __forceinline__ void loadB(const __half* gh, const __half* gl, int n16,
                                      uint32_t dst, int tid) {
    for (int j = tid; j < n16; j += STHR) {
        cp16(dst + j*16, (const char*)gh + j*16);
        cp16(dst + 8448 + j*16, (const char*)gl + j*16);
    }
    CP_COMMIT();
}

// flat chunk prefetch: fj in [0,33). fj>=33 -> empty commit group (keeps wait count uniform)
__device__ __forceinline__ void prefetchFlat(int nd, int fj, uint32_t bufbase, int tid) {
    if (fj < 9) {
        loadB(g_W1h + ((size_t)nd*9 + fj)*16*LDB, g_W1l + ((size_t)nd*9 + fj)*16*LDB,
              528, bufbase + (uint32_t)(fj & 3)*BUF_STRIDE, tid);
    } else if (fj < 25) {
        int j = fj - 9;
        loadB(g_W2h + ((size_t)nd*16 + j)*16*LDB, g_W2l + ((size_t)nd*16 + j)*16*LDB,
              528, bufbase + (uint32_t)(fj & 3)*BUF_STRIDE, tid);
    } else if (fj < NCHUNK) {
        int j = fj - 25;   // k32 chunk = two consecutive k16 rows-blocks (contiguous)
        loadB(g_W3h + ((size_t)nd*16 + 2*j)*16*LDB3, g_W3l + ((size_t)nd*16 + 2*j)*16*LDB3,
              288, bufbase + (uint32_t)(fj & 3)*BUF_STRIDE, tid);
    } else {
        CP_COMMIT();   // empty group
    }
}

// compute one k16 chunk, N=256 (warp tile 32x64); pass-major mma order
__device__ __forceinline__ void chunk256(uint32_t aHaddr, uint32_t aLaddr,
                                         uint32_t bBase, float (&acc)[2][8][4]) {
    uint32_t ah[2][4], al[2][4];
    ldsm4(aHaddr, ah[0]); ldsm4(aHaddr + 16*LDA*2, ah[1]);
    ldsm4(aLaddr, al[0]); ldsm4(aLaddr + 16*LDA*2, al[1]);
#pragma unroll
    for (int g = 0; g < 4; g++) {
        uint32_t bh[4], bl[4];
        ldsm4t(bBase + g*32, bh);
        ldsm4t(bBase + 8448 + g*32, bl);
#pragma unroll
        for (int mf = 0; mf < 2; mf++)
#pragma unroll
            for (int s = 0; s < 2; s++)
                mma16816(acc[mf][2*g + s], ah[mf], bh[2*s], bh[2*s+1]);
#pragma unroll
        for (int mf = 0; mf < 2; mf++)
#pragma unroll
            for (int s = 0; s < 2; s++)
                mma16816(acc[mf][2*g + s], ah[mf], bl[2*s], bl[2*s+1]);
#pragma unroll
        for (int mf = 0; mf < 2; mf++)
#pragma unroll
            for (int s = 0; s < 2; s++)
                mma16816(acc[mf][2*g + s], al[mf], bh[2*s], bh[2*s+1]);
    }
}
// compute one k16 sub-chunk, N=64 (warp tile 32x16); pass-major order
__device__ __forceinline__ void chunk64(uint32_t aHaddr, uint32_t aLaddr,
                                        uint32_t bBase, float (&acc)[2][8][4]) {
    uint32_t ah[2][4], al[2][4], bh[4], bl[4];
    ldsm4(aHaddr, ah[0]); ldsm4(aHaddr + 16*LDA*2, ah[1]);
    ldsm4(aLaddr, al[0]); ldsm4(aLaddr + 16*LDA*2, al[1]);
    ldsm4t(bBase, bh);
    ldsm4t(bBase + 8448, bl);
#pragma unroll
    for (int mf = 0; mf < 2; mf++)
#pragma unroll
        for (int s = 0; s < 2; s++)
            mma16816(acc[mf][s], ah[mf], bh[2*s], bh[2*s+1]);
#pragma unroll
    for (int mf = 0; mf < 2; mf++)
#pragma unroll
        for (int s = 0; s < 2; s++)
            mma16816(acc[mf][s], ah[mf], bl[2*s], bl[2*s+1]);
#pragma unroll
    for (int mf = 0; mf < 2; mf++)
#pragma unroll
        for (int s = 0; s < 2; s++)
            mma16816(acc[mf][s], al[mf], bh[2*s], bh[2*s+1]);
}

// epilogue: relu(acc+bias) -> fp16 split -> store into A buffers; zero acc
__device__ __forceinline__ void epiA(float (&acc)[2][8][4], const float* sb,
                                     char* sm, int m0, int n0, int lane) {
#pragma unroll
    for (int mf = 0; mf < 2; mf++)
#pragma unroll
        for (int nf = 0; nf < 8; nf++) {
            int col = n0 + 8*nf + (lane & 3)*2;
            float bx = sb[col], by = sb[col+1];
            int r0 = m0 + 16*mf + (lane >> 2);
            float v00 = fmaxf(acc[mf][nf][0] + bx, 0.f);
            float v01 = fmaxf(acc[mf][nf][1] + by, 0.f);
            float v10 = fmaxf(acc[mf][nf][2] + bx, 0.f);
            float v11 = fmaxf(acc[mf][nf][3] + by, 0.f);
            __half h00 = __float2half_rn(v00), h01 = __float2half_rn(v01);
            __half h10 = __float2half_rn(v10), h11 = __float2half_rn(v11);
            *(__half2*)(sm + OFF_AH + ((size_t)r0*LDA + col)*2)     = __halves2half2(h00, h01);
            *(__half2*)(sm + OFF_AH + ((size_t)(r0+8)*LDA + col)*2) = __halves2half2(h10, h11);
            *(__half2*)(sm + OFF_AL + ((size_t)r0*LDA + col)*2) =
                __halves2half2(__float2half_rn(v00 - __half2float(h00)),
                               __float2half_rn(v01 - __half2float(h01)));
            *(__half2*)(sm + OFF_AL + ((size_t)(r0+8)*LDA + col)*2) =
                __halves2half2(__float2half_rn(v10 - __half2float(h10)),
                               __float2half_rn(v11 - __half2float(h11)));
            acc[mf][nf][0] = acc[mf][nf][1] = acc[mf][nf][2] = acc[mf][nf][3] = 0.f;
        }
}

// ---------------- one recurrent timestep (mma.sync, 4-deep B pipeline) ----------------
__global__ void __launch_bounds__(STHR, 1) step3_kernel(
    const float* __restrict__ x,
    const float* __restrict__ b1, const float* __restrict__ b2,
    const float* __restrict__ b3, int t)
{
    extern __shared__ char sm[];
    const uint32_t smb = smem_to_u32(sm);

    const int tid = threadIdx.x, lane = tid & 31, wid = tid >> 5;
    const int mw = wid >> 2, nwc = wid & 3;      // warp grid 4x4
    const int m0 = mw * 32;
    const int n0 = nwc * 64;                     // N=256 layers
    const int n03 = nwc * 16;                    // N=64 layer
    const int nd = blockIdx.y;
    const int b0 = blockIdx.x * SM_M;
    const int rd = t & 1, wrp = rd ^ 1;
    const int p0 = c_par[nd][0], p1 = c_par[nd][1];

    float* sB1 = (float*)(sm + OFF_BIAS);
    float* sB2 = (float*)(sm + OFF_BIAS + 1024);
    float* sB3 = (float*)(sm + OFF_BIAS + 2048);
    if (tid < 256) { sB1[tid] = b1[nd*F0 + tid]; sB2[tid] = b2[nd*F0 + tid]; }
    if (tid < 64)  sB3[tid] = b3[nd*FML + tid];

    // per-thread ldmatrix base addresses
    const int rowoff = ((lane >> 3) & 1)*8 + (lane & 7);
    const int koffA  = (lane >> 4)*8;
    const uint32_t aH0 = smb + OFF_AH + (((uint32_t)(m0 + rowoff))*LDA + koffA)*2;
    const uint32_t aL0 = smb + OFF_AL + (((uint32_t)(m0 + rowoff))*LDA + koffA)*2;
    const uint32_t bRow = ((lane >> 3) & 1)*8 + (lane & 7);
    const uint32_t bCol = (uint32_t)(lane >> 4)*8;
    const uint32_t bOffL12 = (bRow*LDB + n0 + bCol)*2;
    const uint32_t bOffL3  = (bRow*LDB3 + n03 + bCol)*2;
    const uint32_t bufbase = smb + OFF_B;

    float acc[2][8][4];
#pragma unroll
    for (int a = 0; a < 2; a++)
#pragma unroll
        for (int b = 0; b < 8; b++)
#pragma unroll
            for (int c = 0; c < 4; c++) acc[a][b][c] = 0.f;

    // prefetch chunks 0..2 (3 groups in flight)
    prefetchFlat(nd, 0, bufbase, tid);
    prefetchFlat(nd, 1, bufbase, tid);
    prefetchFlat(nd, 2, bufbase, tid);

    // gather L1 input A (fp16 split): cols 0..143 (130..143 zero)
    {
        const float* Sp0 = &g_state2[rd][p0][0][0];
        const float* Sp1 = &g_state2[rd][p1][0][0];
        for (int i = tid; i < SM_M*K1; i += STHR) {
            int r = i / K1, c = i % K1;
            float v = 0.f;
            if (c < 2)        v = x[(size_t)(b0 + r)*(NNODE*T_TOT) + (c ? p1 : p0)*T_TOT + t];
            else if (c < 66)  v = Sp0[(size_t)(b0 + r)*FML + (c - 2)];
            else if (c < 130) v = Sp1[(size_t)(b0 + r)*FML + (c - 66)];
            __half h = __float2half_rn(v);
            *(__half*)(sm + OFF_AH + ((size_t)r*LDA + c)*2) = h;
            *(__half*)(sm + OFF_AL + ((size_t)r*LDA + c)*2) = __float2half_rn(v - __half2float(h));
        }
    }

    // ===== LAYER 1: flat chunks 0..8 =====
    for (int kc = 0; kc < 9; kc++) {
        __syncthreads();                       // buffer-reuse + (kc=0) gather visibility
        prefetchFlat(nd, kc + 3, bufbase, tid);
        CP_WAIT3();                            // chunk kc's group complete
        chunk256(aH0 + kc*32, aL0 + kc*32,
                 bufbase + (uint32_t)(kc & 3)*BUF_STRIDE + bOffL12, acc);
    }
    __syncthreads();
    epiA(acc, sB1, sm, m0, n0, lane);

    // ===== LAYER 2: flat chunks 9..24 =====
    for (int kc = 0; kc < 16; kc++) {
        const int fj = 9 + kc;
        __syncthreads();                       // (kc=0) also separates epi writes from reads
        prefetchFlat(nd, fj + 3, bufbase, tid);
        CP_WAIT3();
        chunk256(aH0 + kc*32, aL0 + kc*32,
                 bufbase + (uint32_t)(fj & 3)*BUF_STRIDE + bOffL12, acc);
    }
    __syncthreads();
    epiA(acc, sB2, sm, m0, n0, lane);

    // ===== LAYER 3: flat chunks 25..32 (k32 each = 2 x k16 subs) =====
    for (int kc = 0; kc < 8; kc++) {
        const int fj = 25 + kc;
        __syncthreads();
        prefetchFlat(nd, fj + 3, bufbase, tid);   // fj+3 >= 33 -> empty commit
        CP_WAIT3();
        uint32_t bb = bufbase + (uint32_t)(fj & 3)*BUF_STRIDE + bOffL3;
        chunk64(aH0 + (2*kc)*32,   aL0 + (2*kc)*32,   bb,        acc);
        chunk64(aH0 + (2*kc+1)*32, aL0 + (2*kc+1)*32, bb + 2304, acc);   // +16*LDB3*2
    }

    // epilogue: state = tanh(acc + b3)
    float* gS = &g_state2[wrp][nd][0][0];
#pragma unroll
    for (int mf = 0; mf < 2; mf++)
#pragma unroll
        for (int nf = 0; nf < 2; nf++) {
            int col = n03 + 8*nf + (lane & 3)*2;
            float bx = sB3[col], by = sB3[col+1];
            int r0 = m0 + 16*mf + (lane >> 2);
            float2 o0, o1;
            o0.x = tanhf(acc[mf][nf][0] + bx);
            o0.y = tanhf(acc[mf][nf][1] + by);
            o1.x = tanhf(acc[mf][nf][2] + bx);
            o1.y = tanhf(acc[mf][nf][3] + by);
            *(float2*)(gS + (size_t)(b0 + r0)*FML + col)     = o0;
            *(float2*)(gS + (size_t)(b0 + r0 + 8)*FML + col) = o1;
        }
}

// ---------------- final head (SIMT) ----------------
__device__ __forceinline__ void ldw256(const float* __restrict__ gW, int K, int kbase,
                                       int tid, float4* pre) {
#pragma unroll
    for (int p = 0; p < 4; p++) {
        int q = p*NTHR + tid, row = q >> 6, c4 = q & 63;
        float4 v = make_float4(0.f, 0.f, 0.f, 0.f);
        if (kbase + row < K) v = *(const float4*)(gW + (size_t)(kbase+row)*256 + c4*4);
        pre[p] = v;
    }
}
__device__ __forceinline__ void stw256(float* sW, int tid, const float4* pre) {
#pragma unroll
    for (int p = 0; p < 4; p++) {
        int q = p*NTHR + tid, row = q >> 6, c4 = q & 63;
        *(float4*)(sW + row*256 + c4*4) = pre[p];
    }
}
__device__ __forceinline__ void gemm256(const float* __restrict__ sA, int lda,
                                        const float* __restrict__ gW, int K,
                                        const float* __restrict__ gb,
                                        float* __restrict__ sOut, int ldo,
                                        float* sW, int tid)
{
    const int tm = tid >> 5, tn = tid & 31;
    const int m0 = tm * 8, n0 = tn * 2;
    ull acc[8][4];
#pragma unroll
    for (int i = 0; i < 8; i++)
#pragma unroll
        for (int j = 0; j < 4; j++) acc[i][j] = 0ull;
    const int nt = (K + KT - 1) / KT;
    float4 pre[4];
    ldw256(gW, K, 0, tid, pre);
    stw256(sW, tid, pre);
    __syncthreads();
    for (int kt = 0; kt < nt; kt++) {
        if (kt + 1 < nt) ldw256(gW, K, (kt+1)*KT, tid, pre);
        const float* Wb = sW + (kt & 1) * (KT*256);
        const float* Arow = sA + m0*lda + kt*KT;
#pragma unroll
        for (int kk = 0; kk < KT; kk++) {
            const ull* bp = (const ull*)(Wb + kk*256 + n0);
            ull w0 = bp[0], w1 = bp[32], w2 = bp[64], w3 = bp[96];
#pragma unroll
            for (int i = 0; i < 8; i++) {
                float a = Arow[i*lda + kk];
                ull aa = pack2(a, a);
                acc[i][0] = fma2(aa, w0, acc[i][0]);
                acc[i][1] = fma2(aa, w1, acc[i][1]);
                acc[i][2] = fma2(aa, w2, acc[i][2]);
                acc[i][3] = fma2(aa, w3, acc[i][3]);
            }
        }
        if (kt + 1 < nt) stw256(sW + ((kt+1) & 1)*(KT*256), tid, pre);
        __syncthreads();
    }
    float2 bb[4];
#pragma unroll
    for (int j = 0; j < 4; j++) bb[j] = *(const float2*)(gb + n0 + 64*j);
#pragma unroll
    for (int i = 0; i < 8; i++)
#pragma unroll
        for (int j = 0; j < 4; j++) {
            float2 v = unpack2(acc[i][j]);
            v.x = fmaxf(v.x + bb[j].x, 0.f);
            v.y = fmaxf(v.y + bb[j].y, 0.f);
            *(float2*)(sOut + (m0+i)*ldo + n0 + 64*j) = v;
        }
}

__global__ __launch_bounds__(NTHR) void final1_kernel(
    const float* __restrict__ x,
    const float* __restrict__ Wo1, const float* __restrict__ bo1)
{
    extern __shared__ float smem[];
    float* sF = smem;
    float* sW = sF + TILE_B*LDF;
    const int tid = threadIdx.x;
    const int b0  = blockIdx.x * TILE_B;
    const float* st = &g_state2[0][0][0][0];

    for (int i = tid; i < TILE_B*320; i += NTHR) {
        int m = i / 320, c = i % 320;
        sF[m*LDF + NNODE + c] = st[((size_t)(c >> 6)*B_TOT + (b0+m))*FML + (c & 63)];
    }
    for (int i = tid; i < TILE_B*NNODE; i += NTHR) {
        int m = i / NNODE, nn = i % NNODE;
        sF[m*LDF + nn] = x[(size_t)(b0+m)*(NNODE*T_TOT) + nn*T_TOT + (T_TOT-1)];
    }
    for (int i = tid; i < TILE_B*(LDF-KFEAT); i += NTHR) {
        int m = i / (LDF-KFEAT), c = KFEAT + i % (LDF-KFEAT);
        sF[m*LDF + c] = 0.f;
    }
    __syncthreads();
    gemm256(sF, LDF, Wo1, KFEAT, bo1, sF, LDF, sW, tid);
    __syncthreads();
    for (int i = tid; i < TILE_B*F0; i += NTHR) {
        int m = i >> 8, c = i & 255;
        g_h[(size_t)(b0+m)*F0 + c] = sF[m*LDF + c];
    }
    float s = 0.f, q = 0.f;
    for (int m = 0; m < TILE_B; m++) {
        float v = sF[m*LDF + tid];
        s += v; q += v*v;
    }
    g_psum[blockIdx.x*F0 + tid] = s;
    g_psq [blockIdx.x*F0 + tid] = q;
}

__global__ void bn_kernel(const float* __restrict__ gamma, const float* __restrict__ beta) {
    int c = threadIdx.x;
    float s = 0.f, q = 0.f;
    for (int b = 0; b < (B_TOT/TILE_B); b++) { s += g_psum[b*F0 + c]; q += g_psq[b*F0 + c]; }
    float mu  = s * (1.f / B_TOT);
    float var = q * (1.f / B_TOT) - mu * mu;
    float sc = gamma[c] * rsqrtf(var + 1e-5f);
    g_scale[c] = sc;
    g_shift[c] = beta[c] - mu * sc;
}

__global__ __launch_bounds__(NTHR) void final2_kernel(
    const float* __restrict__ Wo2, const float* __restrict__ bo2, float* __restrict__ out)
{
    __shared__ float sw2[F0*7], sb2[7], ssc[F0], ssh[F0];
    const int tid = threadIdx.x;
    for (int i = tid; i < F0*7; i += NTHR) sw2[i] = Wo2[i];
    if (tid < 7) sb2[tid] = bo2[tid];
    ssc[tid] = g_scale[tid];
    ssh[tid] = g_shift[tid];
    __syncthreads();
    const int warp = tid >> 5, lane = tid & 31;
    for (int r = 0; r < 16; r++) {
        int b = blockIdx.x*128 + warp*16 + r;
        float a0=0,a1=0,a2=0,a3=0,a4=0,a5=0,a6=0;
        const float* hp = g_h + (size_t)b*F0;
#pragma unroll
        for (int kk = 0; kk < 8; kk++) {
            int k = kk*32 + lane;
            float hv = hp[k]*ssc[k] + ssh[k];
            const float* wrp2 = sw2 + k*7;
            a0 += hv*wrp2[0]; a1 += hv*wrp2[1]; a2 += hv*wrp2[2]; a3 += hv*wrp2[3];
            a4 += hv*wrp2[4]; a5 += hv*wrp2[5]; a6 += hv*wrp2[6];
        }
#pragma unroll
        for (int off = 16; off; off >>= 1) {
            a0 += __shfl_down_sync(0xffffffffu, a0, off);
            a1 += __shfl_down_sync(0xffffffffu, a1, off);
            a2 += __shfl_down_sync(0xffffffffu, a2, off);
            a3 += __shfl_down_sync(0xffffffffu, a3, off);
            a4 += __shfl_down_sync(0xffffffffu, a4, off);
            a5 += __shfl_down_sync(0xffffffffu, a5, off);
            a6 += __shfl_down_sync(0xffffffffu, a6, off);
        }
        if (lane == 0) {
            float l[7] = { a0+sb2[0], a1+sb2[1], a2+sb2[2], a3+sb2[3], a4+sb2[4], a5+sb2[5], a6+sb2[6] };
            float mx = l[0];
#pragma unroll
            for (int j = 1; j < 7; j++) mx = fmaxf(mx, l[j]);
            float e[7], se = 0.f;
#pragma unroll
            for (int j = 0; j < 7; j++) { e[j] = expf(l[j] - mx); se += e[j]; }
            float inv = 1.f / se;
#pragma unroll
            for (int j = 0; j < 7; j++) out[(size_t)b*7 + j] = e[j]*inv;
        }
    }
}

__global__ void zero_state_kernel() {
    size_t n = (size_t)NNODE*B_TOT*FML;
    float* p = &g_state2[0][0][0][0];
    for (size_t i = blockIdx.x*(size_t)blockDim.x + threadIdx.x; i < n;
         i += (size_t)gridDim.x*blockDim.x) p[i] = 0.f;
}

extern "C" void kernel_launch(void* const* d_in, const int* in_sizes, int n_in,
                              void* d_out, int out_size)
{
    (void)in_sizes; (void)n_in; (void)out_size;
    const float* x     = (const float*)d_in[0];
    const float* W1    = (const float*)d_in[1];
    const float* b1    = (const float*)d_in[2];
    const float* W2    = (const float*)d_in[3];
    const float* b2    = (const float*)d_in[4];
    const float* W3    = (const float*)d_in[5];
    const float* b3    = (const float*)d_in[6];
    const float* Wo1   = (const float*)d_in[7];
    const float* bo1   = (const float*)d_in[8];
    const float* gamma = (const float*)d_in[9];
    const float* beta  = (const float*)d_in[10];
    const float* Wo2   = (const float*)d_in[11];
    const float* bo2   = (const float*)d_in[12];
    float* out = (float*)d_out;

    const int F1_SMEM = (TILE_B*LDF + 2*KT*256) * (int)sizeof(float);
    cudaFuncSetAttribute(step3_kernel,  cudaFuncAttributeMaxDynamicSharedMemorySize, STEP_SMEM);
    cudaFuncSetAttribute(final1_kernel, cudaFuncAttributeMaxDynamicSharedMemorySize, F1_SMEM);

    prep_kernel<<<512, 256>>>(W1, W2, W3);
    zero_state_kernel<<<512, 256>>>();

    dim3 sgrid(B_TOT/SM_M, NNODE);   // (64, 5) = 320 CTAs, 1 per SM
    for (int t = 0; t < T_TOT; t++)
        step3_kernel<<<sgrid, STHR, STEP_SMEM>>>(x, b1, b2, b3, t);

    final1_kernel<<<B_TOT/TILE_B, NTHR, F1_SMEM>>>(x, Wo1, bo1);
    bn_kernel<<<1, F0>>>(gamma, beta);
    final2_kernel<<<64, NTHR>>>(Wo2, bo2, out);
}

// round 10
// speedup vs baseline: 2.1354x; 2.1354x over previous
#include <cuda_runtime.h>
#include <cuda_fp16.h>
#include <math.h>
#include <stdint.h>

typedef unsigned long long ull;

#define B_TOT 8192
#define T_TOT 128
#define NNODE 5
#define FML   64
#define F0    256
#define DIN   130
#define KFEAT 325
#define TILE_B 64
#define NTHR   256
#define KT     16
#define LDF    336

#define SM_M   64         // batch rows per step CTA (2 CTAs/SM)
#define STHR   256        // 8 warps: 2 M-bands x 4 N-cols
#define LDA    264        // A row pitch in halves (528B)
#define LDB    264        // B chunk row pitch (L1/L2)
#define LDB3   72         // B chunk row pitch (L3)
#define K1     144        // padded K of layer1

__constant__ int c_par[NNODE][2] = {{3,4},{0,4},{0,1},{1,2},{2,3}};

// ---------------- device scratch ----------------
__device__ float g_state2[2][NNODE][B_TOT][FML];
__device__ float g_h[(size_t)B_TOT*F0];
__device__ float g_psum[(B_TOT/TILE_B)*F0];
__device__ float g_psq [(B_TOT/TILE_B)*F0];
__device__ float g_scale[F0], g_shift[F0];
// fp16 weights (B side plain fp16; accuracy comes from A hi/lo split)
__device__ __half g_W1h[5*9*16*LDB];
__device__ __half g_W2h[5*16*16*LDB];
__device__ __half g_W3h[5*16*16*LDB3];

// ---------------- f32x2 helpers (final head GEMM) ----------------
__device__ __forceinline__ ull fma2(ull a, ull b, ull c) {
    ull d; asm("fma.rn.f32x2 %0, %1, %2, %3;" : "=l"(d) : "l"(a), "l"(b), "l"(c)); return d;
}
__device__ __forceinline__ ull pack2(float x, float y) {
    ull d; asm("mov.b64 %0, {%1, %2};" : "=l"(d) : "f"(x), "f"(y)); return d;
}
__device__ __forceinline__ float2 unpack2(ull v) {
    float2 r; asm("mov.b64 {%0, %1}, %2;" : "=f"(r.x), "=f"(r.y) : "l"(v)); return r;
}

// ---------------- tensor-core primitives (baseline PTX, sm_80+) ----------------
__device__ __forceinline__ uint32_t smem_to_u32(const void* p) {
    uint32_t a; asm("{ .reg .u64 t; cvta.to.shared.u64 t, %1; cvt.u32.u64 %0, t; }" : "=r"(a) : "l"(p)); return a;
}
__device__ __forceinline__ void ldsm4(uint32_t a, uint32_t* r) {
    asm volatile("ldmatrix.sync.aligned.m8n8.x4.shared.b16 {%0,%1,%2,%3}, [%4];"
        : "=r"(r[0]), "=r"(r[1]), "=r"(r[2]), "=r"(r[3]) : "r"(a));
}
__device__ __forceinline__ void ldsm4t(uint32_t a, uint32_t* r) {
    asm volatile("ldmatrix.sync.aligned.m8n8.x4.trans.shared.b16 {%0,%1,%2,%3}, [%4];"
        : "=r"(r[0]), "=r"(r[1]), "=r"(r[2]), "=r"(r[3]) : "r"(a));
}
__device__ __forceinline__ void mma16816(float* c, const uint32_t* a, uint32_t b0, uint32_t b1) {
    asm volatile("mma.sync.aligned.m16n8k16.row.col.f32.f16.f16.f32 "
        "{%0,%1,%2,%3}, {%4,%5,%6,%7}, {%8,%9}, {%0,%1,%2,%3};"
        : "+f"(c[0]), "+f"(c[1]), "+f"(c[2]), "+f"(c[3])
        : "r"(a[0]), "r"(a[1]), "r"(a[2]), "r"(a[3]), "r"(b0), "r"(b1));
}
__device__ __forceinline__ void cp16(uint32_t dst, const void* src) {
    asm volatile("cp.async.cg.shared.global [%0], [%1], 16;" :: "r"(dst), "l"(src));
}
#define CP_COMMIT() asm volatile("cp.async.commit_group;" ::: "memory")
#define CP_WAIT0()  asm volatile("cp.async.wait_group 0;" ::: "memory")

// smem byte offsets (SM_M = 64, B fp16-only)
#define OFF_AH   0
#define OFF_AL   33792                 // 64*264*2
#define OFF_B    67584                 // 2 buffers x 8448B
#define BUF_STRIDE 8448
#define OFF_BIAS 84480                 // b1 (1024B) | b2 (1024B) | b3 (256B)
#define STEP_SMEM (84480 + 2304)

// ---------------- weight prep: transpose-to-chunks + fp16 round ----------------
__global__ void prep_kernel(const float* __restrict__ W1, const float* __restrict__ W2,
                            const float* __restrict__ W3) {
    int i0 = blockIdx.x*blockDim.x + threadIdx.x, gs = gridDim.x*blockDim.x;
    for (int i = i0; i < 5*9*16*LDB; i += gs) {        // W1: [nd][9][16][264]
        int nd = i/(9*16*LDB), r = i%(9*16*LDB);
        int kc = r/(16*LDB), q = r%(16*LDB), kr = q/LDB, n = q%LDB;
        int k = kc*16 + kr;
        float v = (k < DIN && n < F0) ? W1[((size_t)nd*DIN + k)*F0 + n] : 0.f;
        g_W1h[i] = __float2half_rn(v);
    }
    for (int i = i0; i < 5*16*16*LDB; i += gs) {       // W2: [nd][16][16][264]
        int nd = i/(16*16*LDB), r = i%(16*16*LDB);
        int kc = r/(16*LDB), q = r%(16*LDB), kr = q/LDB, n = q%LDB;
        int k = kc*16 + kr;
        float v = (n < F0) ? W2[((size_t)nd*F0 + k)*F0 + n] : 0.f;
        g_W2h[i] = __float2half_rn(v);
    }
    for (int i = i0; i < 5*16*16*LDB3; i += gs) {      // W3: [nd][16][16][72]
        int nd = i/(16*16*LDB3), r = i%(16*16*LDB3);
        int kc = r/(16*LDB3), q = r%(16*LDB3), kr = q/LDB3, n = q%LDB3;
        int k = kc*16 + kr;
        float v = (n < FML) ? W3[((size_t)nd*F0 + k)*FML + n] : 0.f;
        g_W3h[i] = __float2half_rn(v);
    }
}

// B chunk loader: linear 16B copies, one commit group. n16 = 16B units.
__device__ __forceinline__ void loadB(const __half* gh, int n16, uint32_t dst, int tid) {
    for (int j = tid; j < n16; j += STHR) cp16(dst + j*16, (const char*)gh + j*16);
    CP_COMMIT();
}

// compute one k16 chunk, N=256 (warp tile 32x64); 2-pass (a·bh via ah,al), pass-major
__device__ __forceinline__ void chunk256(uint32_t aHaddr, uint32_t aLaddr,
                                         uint32_t bBase, float (&acc)[2][8][4]) {
    uint32_t ah[2][4], al[2][4];
    ldsm4(aHaddr, ah[0]); ldsm4(aHaddr + 16*LDA*2, ah[1]);
    ldsm4(aLaddr, al[0]); ldsm4(aLaddr + 16*LDA*2, al[1]);
#pragma unroll
    for (int g = 0; g < 4; g++) {
        uint32_t bh[4];
        ldsm4t(bBase + g*32, bh);
#pragma unroll
        for (int mf = 0; mf < 2; mf++)
#pragma unroll
            for (int s = 0; s < 2; s++)
                mma16816(acc[mf][2*g + s], ah[mf], bh[2*s], bh[2*s+1]);
#pragma unroll
        for (int mf = 0; mf < 2; mf++)
#pragma unroll
            for (int s = 0; s < 2; s++)
                mma16816(acc[mf][2*g + s], al[mf], bh[2*s], bh[2*s+1]);
    }
}
// compute one k16 chunk, N=64 (warp tile 32x16); 2-pass
__device__ __forceinline__ void chunk64(uint32_t aHaddr, uint32_t aLaddr,
                                        uint32_t bBase, float (&acc)[2][8][4]) {
    uint32_t ah[2][4], al[2][4], bh[4];
    ldsm4(aHaddr, ah[0]); ldsm4(aHaddr + 16*LDA*2, ah[1]);
    ldsm4(aLaddr, al[0]); ldsm4(aLaddr + 16*LDA*2, al[1]);
    ldsm4t(bBase, bh);
#pragma unroll
    for (int mf = 0; mf < 2; mf++)
#pragma unroll
        for (int s = 0; s < 2; s++)
            mma16816(acc[mf][s], ah[mf], bh[2*s], bh[2*s+1]);
#pragma unroll
    for (int mf = 0; mf < 2; mf++)
#pragma unroll
        for (int s = 0; s < 2; s++)
            mma16816(acc[mf][s], al[mf], bh[2*s], bh[2*s+1]);
}

// epilogue: relu(acc+bias) -> fp16 split -> store into A buffers; zero acc
__device__ __forceinline__ void epiA(float (&acc)[2][8][4], const float* sb,
                                     char* sm, int m0, int n0, int lane) {
#pragma unroll
    for (int mf = 0; mf < 2; mf++)
#pragma unroll
        for (int nf = 0; nf < 8; nf++) {
            int col = n0 + 8*nf + (lane & 3)*2;
            float bx = sb[col], by = sb[col+1];
            int r0 = m0 + 16*mf + (lane >> 2);
            float v00 = fmaxf(acc[mf][nf][0] + bx, 0.f);
            float v01 = fmaxf(acc[mf][nf][1] + by, 0.f);
            float v10 = fmaxf(acc[mf][nf][2] + bx, 0.f);
            float v11 = fmaxf(acc[mf][nf][3] + by, 0.f);
            __half h00 = __float2half_rn(v00), h01 = __float2half_rn(v01);
            __half h10 = __float2half_rn(v10), h11 = __float2half_rn(v11);
            *(__half2*)(sm + OFF_AH + ((size_t)r0*LDA + col)*2)     = __halves2half2(h00, h01);
            *(__half2*)(sm + OFF_AH + ((size_t)(r0+8)*LDA + col)*2) = __halves2half2(h10, h11);
            *(__half2*)(sm + OFF_AL + ((size_t)r0*LDA + col)*2) =
                __halves2half2(__float2half_rn(v00 - __half2float(h00)),
                               __float2half_rn(v01 - __half2float(h01)));
            *(__half2*)(sm + OFF_AL + ((size_t)(r0+8)*LDA + col)*2) =
                __halves2half2(__float2half_rn(v10 - __half2float(h10)),
                               __float2half_rn(v11 - __half2float(h11)));
            acc[mf][nf][0] = acc[mf][nf][1] = acc[mf][nf][2] = acc[mf][nf][3] = 0.f;
        }
}

// ---------------- one recurrent timestep (mma.sync, 2 CTAs/SM, 2-pass) ----------------
__global__ void __launch_bounds__(STHR, 2) step3_kernel(
    const float* __restrict__ x,
    const float* __restrict__ b1, const float* __restrict__ b2,
    const float* __restrict__ b3, int t)
{
    extern __shared__ char sm[];
    const uint32_t smb = smem_to_u32(sm);

    const int tid = threadIdx.x, lane = tid & 31, wid = tid >> 5;
    const int mw = wid >> 2, nwc = wid & 3;      // warp grid 2x4
    const int m0 = mw * 32;
    const int n0 = nwc * 64;                     // N=256 layers
    const int n03 = nwc * 16;                    // N=64 layer
    const int nd = blockIdx.y;
    const int b0 = blockIdx.x * SM_M;
    const int rd = t & 1, wrp = rd ^ 1;
    const int p0 = c_par[nd][0], p1 = c_par[nd][1];

    float* sB1 = (float*)(sm + OFF_BIAS);
    float* sB2 = (float*)(sm + OFF_BIAS + 1024);
    float* sB3 = (float*)(sm + OFF_BIAS + 2048);
    if (tid < 256) { sB1[tid] = b1[nd*F0 + tid]; sB2[tid] = b2[nd*F0 + tid]; }
    if (tid < 64)  sB3[tid] = b3[nd*FML + tid];

    // per-thread ldmatrix base addresses
    const int rowoff = ((lane >> 3) & 1)*8 + (lane & 7);
    const int koffA  = (lane >> 4)*8;
    const uint32_t aH0 = smb + OFF_AH + (((uint32_t)(m0 + rowoff))*LDA + koffA)*2;
    const uint32_t aL0 = smb + OFF_AL + (((uint32_t)(m0 + rowoff))*LDA + koffA)*2;
    const uint32_t bRow = ((lane >> 3) & 1)*8 + (lane & 7);
    const uint32_t bCol = (uint32_t)(lane >> 4)*8;
    const uint32_t bOffL12 = (bRow*LDB + n0 + bCol)*2;
    const uint32_t bOffL3  = (bRow*LDB3 + n03 + bCol)*2;
    const uint32_t bufA[2] = { smb + OFF_B, smb + OFF_B + BUF_STRIDE };

    float acc[2][8][4];
#pragma unroll
    for (int a = 0; a < 2; a++)
#pragma unroll
        for (int b = 0; b < 8; b++)
#pragma unroll
            for (int c = 0; c < 4; c++) acc[a][b][c] = 0.f;

    // prefetch L1 chunk0 into buf0
    loadB(g_W1h + ((size_t)nd*9)*16*LDB, 528, bufA[0], tid);

    // gather L1 input A (fp16 split): cols 0..143 (130..143 zero)
    {
        const float* Sp0 = &g_state2[rd][p0][0][0];
        const float* Sp1 = &g_state2[rd][p1][0][0];
        for (int i = tid; i < SM_M*K1; i += STHR) {
            int r = i / K1, c = i % K1;
            float v = 0.f;
            if (c < 2)        v = x[(size_t)(b0 + r)*(NNODE*T_TOT) + (c ? p1 : p0)*T_TOT + t];
            else if (c < 66)  v = Sp0[(size_t)(b0 + r)*FML + (c - 2)];
            else if (c < 130) v = Sp1[(size_t)(b0 + r)*FML + (c - 66)];
            __half h = __float2half_rn(v);
            *(__half*)(sm + OFF_AH + ((size_t)r*LDA + c)*2) = h;
            *(__half*)(sm + OFF_AL + ((size_t)r*LDA + c)*2) = __float2half_rn(v - __half2float(h));
        }
    }

    // ===== LAYER 1: 9 chunks =====
    for (int kc = 0; kc < 9; kc++) {
        CP_WAIT0();
        __syncthreads();
        if (kc + 1 < 9)
            loadB(g_W1h + ((size_t)nd*9 + kc + 1)*16*LDB, 528, bufA[(kc+1)&1], tid);
        chunk256(aH0 + kc*32, aL0 + kc*32, bufA[kc&1] + bOffL12, acc);
    }
    // prefetch L2 chunk0 into buf1 (buf1 last read at kc=7, guarded by kc=8 sync)
    loadB(g_W2h + ((size_t)nd*16)*16*LDB, 528, bufA[1], tid);
    __syncthreads();
    epiA(acc, sB1, sm, m0, n0, lane);

    // ===== LAYER 2: 16 chunks =====
    for (int kc = 0; kc < 16; kc++) {
        CP_WAIT0();
        __syncthreads();
        if (kc + 1 < 16)
            loadB(g_W2h + ((size_t)nd*16 + kc + 1)*16*LDB, 528, bufA[kc&1], tid);
        chunk256(aH0 + kc*32, aL0 + kc*32, bufA[(kc+1)&1] + bOffL12, acc);
    }
    // prefetch L3 chunk0 into buf1
    loadB(g_W3h + ((size_t)nd*16)*16*LDB3, 144, bufA[1], tid);
    __syncthreads();
    epiA(acc, sB2, sm, m0, n0, lane);

    // ===== LAYER 3: 16 chunks, N=64 =====
    for (int kc = 0; kc < 16; kc++) {
        CP_WAIT0();
        __syncthreads();
        if (kc + 1 < 16)
            loadB(g_W3h + ((size_t)nd*16 + kc + 1)*16*LDB3, 144, bufA[kc&1], tid);
        chunk64(aH0 + kc*32, aL0 + kc*32, bufA[(kc+1)&1] + bOffL3, acc);
    }

    // epilogue: state = tanh(acc + b3)
    float* gS = &g_state2[wrp][nd][0][0];
#pragma unroll
    for (int mf = 0; mf < 2; mf++)
#pragma unroll
        for (int nf = 0; nf < 2; nf++) {
            int col = n03 + 8*nf + (lane & 3)*2;
            float bx = sB3[col], by = sB3[col+1];
            int r0 = m0 + 16*mf + (lane >> 2);
            float2 o0, o1;
            o0.x = tanhf(acc[mf][nf][0] + bx);
            o0.y = tanhf(acc[mf][nf][1] + by);
            o1.x = tanhf(acc[mf][nf][2] + bx);
            o1.y = tanhf(acc[mf][nf][3] + by);
            *(float2*)(gS + (size_t)(b0 + r0)*FML + col)     = o0;
            *(float2*)(gS + (size_t)(b0 + r0 + 8)*FML + col) = o1;
        }
}

// ---------------- final head (SIMT) ----------------
__device__ __forceinline__ void ldw256(const float* __restrict__ gW, int K, int kbase,
                                       int tid, float4* pre) {
#pragma unroll
    for (int p = 0; p < 4; p++) {
        int q = p*NTHR + tid, row = q >> 6, c4 = q & 63;
        float4 v = make_float4(0.f, 0.f, 0.f, 0.f);
        if (kbase + row < K) v = *(const float4*)(gW + (size_t)(kbase+row)*256 + c4*4);
        pre[p] = v;
    }
}
__device__ __forceinline__ void stw256(float* sW, int tid, const float4* pre) {
#pragma unroll
    for (int p = 0; p < 4; p++) {
        int q = p*NTHR + tid, row = q >> 6, c4 = q & 63;
        *(float4*)(sW + row*256 + c4*4) = pre[p];
    }
}
__device__ __forceinline__ void gemm256(const float* __restrict__ sA, int lda,
                                        const float* __restrict__ gW, int K,
                                        const float* __restrict__ gb,
                                        float* __restrict__ sOut, int ldo,
                                        float* sW, int tid)
{
    const int tm = tid >> 5, tn = tid & 31;
    const int m0 = tm * 8, n0 = tn * 2;
    ull acc[8][4];
#pragma unroll
    for (int i = 0; i < 8; i++)
#pragma unroll
        for (int j = 0; j < 4; j++) acc[i][j] = 0ull;
    const int nt = (K + KT - 1) / KT;
    float4 pre[4];
    ldw256(gW, K, 0, tid, pre);
    stw256(sW, tid, pre);
    __syncthreads();
    for (int kt = 0; kt < nt; kt++) {
        if (kt + 1 < nt) ldw256(gW, K, (kt+1)*KT, tid, pre);
        const float* Wb = sW + (kt & 1) * (KT*256);
        const float* Arow = sA + m0*lda + kt*KT;
#pragma unroll
        for (int kk = 0; kk < KT; kk++) {
            const ull* bp = (const ull*)(Wb + kk*256 + n0);
            ull w0 = bp[0], w1 = bp[32], w2 = bp[64], w3 = bp[96];
#pragma unroll
            for (int i = 0; i < 8; i++) {
                float a = Arow[i*lda + kk];
                ull aa = pack2(a, a);
                acc[i][0] = fma2(aa, w0, acc[i][0]);
                acc[i][1] = fma2(aa, w1, acc[i][1]);
                acc[i][2] = fma2(aa, w2, acc[i][2]);
                acc[i][3] = fma2(aa, w3, acc[i][3]);
            }
        }
        if (kt + 1 < nt) stw256(sW + ((kt+1) & 1)*(KT*256), tid, pre);
        __syncthreads();
    }
    float2 bb[4];
#pragma unroll
    for (int j = 0; j < 4; j++) bb[j] = *(const float2*)(gb + n0 + 64*j);
#pragma unroll
    for (int i = 0; i < 8; i++)
#pragma unroll
        for (int j = 0; j < 4; j++) {
            float2 v = unpack2(acc[i][j]);
            v.x = fmaxf(v.x + bb[j].x, 0.f);
            v.y = fmaxf(v.y + bb[j].y, 0.f);
            *(float2*)(sOut + (m0+i)*ldo + n0 + 64*j) = v;
        }
}

__global__ __launch_bounds__(NTHR) void final1_kernel(
    const float* __restrict__ x,
    const float* __restrict__ Wo1, const float* __restrict__ bo1)
{
    extern __shared__ float smem[];
    float* sF = smem;
    float* sW = sF + TILE_B*LDF;
    const int tid = threadIdx.x;
    const int b0  = blockIdx.x * TILE_B;
    const float* st = &g_state2[0][0][0][0];

    for (int i = tid; i < TILE_B*320; i += NTHR) {
        int m = i / 320, c = i % 320;
        sF[m*LDF + NNODE + c] = st[((size_t)(c >> 6)*B_TOT + (b0+m))*FML + (c & 63)];
    }
    for (int i = tid; i < TILE_B*NNODE; i += NTHR) {
        int m = i / NNODE, nn = i % NNODE;
        sF[m*LDF + nn] = x[(size_t)(b0+m)*(NNODE*T_TOT) + nn*T_TOT + (T_TOT-1)];
    }
    for (int i = tid; i < TILE_B*(LDF-KFEAT); i += NTHR) {
        int m = i / (LDF-KFEAT), c = KFEAT + i % (LDF-KFEAT);
        sF[m*LDF + c] = 0.f;
    }
    __syncthreads();
    gemm256(sF, LDF, Wo1, KFEAT, bo1, sF, LDF, sW, tid);
    __syncthreads();
    for (int i = tid; i < TILE_B*F0; i += NTHR) {
        int m = i >> 8, c = i & 255;
        g_h[(size_t)(b0+m)*F0 + c] = sF[m*LDF + c];
    }
    float s = 0.f, q = 0.f;
    for (int m = 0; m < TILE_B; m++) {
        float v = sF[m*LDF + tid];
        s += v; q += v*v;
    }
    g_psum[blockIdx.x*F0 + tid] = s;
    g_psq [blockIdx.x*F0 + tid] = q;
}

__global__ void bn_kernel(const float* __restrict__ gamma, const float* __restrict__ beta) {
    int c = threadIdx.x;
    float s = 0.f, q = 0.f;
    for (int b = 0; b < (B_TOT/TILE_B); b++) { s += g_psum[b*F0 + c]; q += g_psq[b*F0 + c]; }
    float mu  = s * (1.f / B_TOT);
    float var = q * (1.f / B_TOT) - mu * mu;
    float sc = gamma[c] * rsqrtf(var + 1e-5f);
    g_scale[c] = sc;
    g_shift[c] = beta[c] - mu * sc;
}

__global__ __launch_bounds__(NTHR) void final2_kernel(
    const float* __restrict__ Wo2, const float* __restrict__ bo2, float* __restrict__ out)
{
    __shared__ float sw2[F0*7], sb2[7], ssc[F0], ssh[F0];
    const int tid = threadIdx.x;
    for (int i = tid; i < F0*7; i += NTHR) sw2[i] = Wo2[i];
    if (tid < 7) sb2[tid] = bo2[tid];
    ssc[tid] = g_scale[tid];
    ssh[tid] = g_shift[tid];
    __syncthreads();
    const int warp = tid >> 5, lane = tid & 31;
    for (int r = 0; r < 16; r++) {
        int b = blockIdx.x*128 + warp*16 + r;
        float a0=0,a1=0,a2=0,a3=0,a4=0,a5=0,a6=0;
        const float* hp = g_h + (size_t)b*F0;
#pragma unroll
        for (int kk = 0; kk < 8; kk++) {
            int k = kk*32 + lane;
            float hv = hp[k]*ssc[k] + ssh[k];
            const float* wrp2 = sw2 + k*7;
            a0 += hv*wrp2[0]; a1 += hv*wrp2[1]; a2 += hv*wrp2[2]; a3 += hv*wrp2[3];
            a4 += hv*wrp2[4]; a5 += hv*wrp2[5]; a6 += hv*wrp2[6];
        }
#pragma unroll
        for (int off = 16; off; off >>= 1) {
            a0 += __shfl_down_sync(0xffffffffu, a0, off);
            a1 += __shfl_down_sync(0xffffffffu, a1, off);
            a2 += __shfl_down_sync(0xffffffffu, a2, off);
            a3 += __shfl_down_sync(0xffffffffu, a3, off);
            a4 += __shfl_down_sync(0xffffffffu, a4, off);
            a5 += __shfl_down_sync(0xffffffffu, a5, off);
            a6 += __shfl_down_sync(0xffffffffu, a6, off);
        }
        if (lane == 0) {
            float l[7] = { a0+sb2[0], a1+sb2[1], a2+sb2[2], a3+sb2[3], a4+sb2[4], a5+sb2[5], a6+sb2[6] };
            float mx = l[0];
#pragma unroll
            for (int j = 1; j < 7; j++) mx = fmaxf(mx, l[j]);
            float e[7], se = 0.f;
#pragma unroll
            for (int j = 0; j < 7; j++) { e[j] = expf(l[j] - mx); se += e[j]; }
            float inv = 1.f / se;
#pragma unroll
            for (int j = 0; j < 7; j++) out[(size_t)b*7 + j] = e[j]*inv;
        }
    }
}

__global__ void zero_state_kernel() {
    size_t n = (size_t)NNODE*B_TOT*FML;
    float* p = &g_state2[0][0][0][0];
    for (size_t i = blockIdx.x*(size_t)blockDim.x + threadIdx.x; i < n;
         i += (size_t)gridDim.x*blockDim.x) p[i] = 0.f;
}

extern "C" void kernel_launch(void* const* d_in, const int* in_sizes, int n_in,
                              void* d_out, int out_size)
{
    (void)in_sizes; (void)n_in; (void)out_size;
    const float* x     = (const float*)d_in[0];
    const float* W1    = (const float*)d_in[1];
    const float* b1    = (const float*)d_in[2];
    const float* W2    = (const float*)d_in[3];
    const float* b2    = (const float*)d_in[4];
    const float* W3    = (const float*)d_in[5];
    const float* b3    = (const float*)d_in[6];
    const float* Wo1   = (const float*)d_in[7];
    const float* bo1   = (const float*)d_in[8];
    const float* gamma = (const float*)d_in[9];
    const float* beta  = (const float*)d_in[10];
    const float* Wo2   = (const float*)d_in[11];
    const float* bo2   = (const float*)d_in[12];
    float* out = (float*)d_out;

    const int F1_SMEM = (TILE_B*LDF + 2*KT*256) * (int)sizeof(float);
    cudaFuncSetAttribute(step3_kernel,  cudaFuncAttributeMaxDynamicSharedMemorySize, STEP_SMEM);
    cudaFuncSetAttribute(final1_kernel, cudaFuncAttributeMaxDynamicSharedMemorySize, F1_SMEM);

    prep_kernel<<<512, 256>>>(W1, W2, W3);
    zero_state_kernel<<<512, 256>>>();

    dim3 sgrid(B_TOT/SM_M, NNODE);   // (128, 5) = 640 CTAs, 2 per SM
    for (int t = 0; t < T_TOT; t++)
        step3_kernel<<<sgrid, STHR, STEP_SMEM>>>(x, b1, b2, b3, t);

    final1_kernel<<<B_TOT/TILE_B, NTHR, F1_SMEM>>>(x, Wo1, bo1);
    bn_kernel<<<1, F0>>>(gamma, beta);
    final2_kernel<<<64, NTHR>>>(Wo2, bo2, out);
}

// round 15
// speedup vs baseline: 2.2428x; 1.0503x over previous
#include <cuda_runtime.h>
#include <cuda_fp16.h>
#include <math.h>
#include <stdint.h>

typedef unsigned long long ull;

#define B_TOT 8192
#define T_TOT 128
#define NNODE 5
#define FML   64
#define F0    256
#define DIN   130
#define KFEAT 325
#define TILE_B 64
#define NTHR   256
#define KT     16
#define LDF    336

#define SM_M   64         // batch rows per step CTA (2 CTAs/SM)
#define STHR   256        // 8 warps: 2 M-bands x 4 N-cols
#define LDA    264        // A row pitch in halves (528B)
#define LDB    264        // B chunk row pitch (L1/L2)
#define LDB3   72         // B chunk row pitch (L3)
#define K1     160        // padded K of layer1 (5 x k32)
#define NFLAT  21         // flat k32 chunks: L1 5 + L2 8 + L3 8

__constant__ int c_par[NNODE][2] = {{3,4},{0,4},{0,1},{1,2},{2,3}};

// ---------------- device scratch ----------------
__device__ float g_state2[2][NNODE][B_TOT][FML];
__device__ float g_h[(size_t)B_TOT*F0];
__device__ float g_psum[(B_TOT/TILE_B)*F0];
__device__ float g_psq [(B_TOT/TILE_B)*F0];
__device__ float g_scale[F0], g_shift[F0];
// fp16 weights, k32-chunked [nd][chunk][32][pitch] (B plain fp16; accuracy via A hi/lo split)
__device__ __half g_W1h[5*5*32*LDB];
__device__ __half g_W2h[5*8*32*LDB];
__device__ __half g_W3h[5*8*32*LDB3];

// ---------------- f32x2 helpers (final head GEMM) ----------------
__device__ __forceinline__ ull fma2(ull a, ull b, ull c) {
    ull d; asm("fma.rn.f32x2 %0, %1, %2, %3;" : "=l"(d) : "l"(a), "l"(b), "l"(c)); return d;
}
__device__ __forceinline__ ull pack2(float x, float y) {
    ull d; asm("mov.b64 %0, {%1, %2};" : "=l"(d) : "f"(x), "f"(y)); return d;
}
__device__ __forceinline__ float2 unpack2(ull v) {
    float2 r; asm("mov.b64 {%0, %1}, %2;" : "=f"(r.x), "=f"(r.y) : "l"(v)); return r;
}

// ---------------- tensor-core primitives (baseline PTX, sm_80+) ----------------
__device__ __forceinline__ uint32_t smem_to_u32(const void* p) {
    uint32_t a; asm("{ .reg .u64 t; cvta.to.shared.u64 t, %1; cvt.u32.u64 %0, t; }" : "=r"(a) : "l"(p)); return a;
}
__device__ __forceinline__ void ldsm4(uint32_t a, uint32_t* r) {
    asm volatile("ldmatrix.sync.aligned.m8n8.x4.shared.b16 {%0,%1,%2,%3}, [%4];"
        : "=r"(r[0]), "=r"(r[1]), "=r"(r[2]), "=r"(r[3]) : "r"(a));
}
__device__ __forceinline__ void ldsm4t(uint32_t a, uint32_t* r) {
    asm volatile("ldmatrix.sync.aligned.m8n8.x4.trans.shared.b16 {%0,%1,%2,%3}, [%4];"
        : "=r"(r[0]), "=r"(r[1]), "=r"(r[2]), "=r"(r[3]) : "r"(a));
}
__device__ __forceinline__ void mma16816(float* c, const uint32_t* a, uint32_t b0, uint32_t b1) {
    asm volatile("mma.sync.aligned.m16n8k16.row.col.f32.f16.f16.f32 "
        "{%0,%1,%2,%3}, {%4,%5,%6,%7}, {%8,%9}, {%0,%1,%2,%3};"
        : "+f"(c[0]), "+f"(c[1]), "+f"(c[2]), "+f"(c[3])
        : "r"(a[0]), "r"(a[1]), "r"(a[2]), "r"(a[3]), "r"(b0), "r"(b1));
}
__device__ __forceinline__ void cp16(uint32_t dst, const void* src) {
    asm volatile("cp.async.cg.shared.global [%0], [%1], 16;" :: "r"(dst), "l"(src));
}
#define CP_COMMIT() asm volatile("cp.async.commit_group;" ::: "memory")
#define CP_WAIT0()  asm volatile("cp.async.wait_group 0;" ::: "memory")

// smem byte offsets (SM_M = 64, B fp16-only, k32 buffers)
#define OFF_AH   0
#define OFF_AL   33792                 // 64*264*2
#define OFF_B    67584                 // 2 buffers x 16896B
#define BUF_STRIDE 16896
#define OFF_BIAS 101376                // b1 (1024B) | b2 (1024B) | b3 (256B)
#define STEP_SMEM (101376 + 2304)

// ---------------- weight prep: transpose-to-k32-chunks + fp16 round ----------------
__global__ void prep_kernel(const float* __restrict__ W1, const float* __restrict__ W2,
                            const float* __restrict__ W3) {
    int i0 = blockIdx.x*blockDim.x + threadIdx.x, gs = gridDim.x*blockDim.x;
    for (int i = i0; i < 5*5*32*LDB; i += gs) {        // W1: [nd][5][32][264]
        int nd = i/(5*32*LDB), r = i%(5*32*LDB);
        int kc = r/(32*LDB), q = r%(32*LDB), kr = q/LDB, n = q%LDB;
        int k = kc*32 + kr;
        float v = (k < DIN && n < F0) ? W1[((size_t)nd*DIN + k)*F0 + n] : 0.f;
        g_W1h[i] = __float2half_rn(v);
    }
    for (int i = i0; i < 5*8*32*LDB; i += gs) {        // W2: [nd][8][32][264]
        int nd = i/(8*32*LDB), r = i%(8*32*LDB);
        int kc = r/(32*LDB), q = r%(32*LDB), kr = q/LDB, n = q%LDB;
        int k = kc*32 + kr;
        float v = (n < F0) ? W2[((size_t)nd*F0 + k)*F0 + n] : 0.f;
        g_W2h[i] = __float2half_rn(v);
    }
    for (int i = i0; i < 5*8*32*LDB3; i += gs) {       // W3: [nd][8][32][72]
        int nd = i/(8*32*LDB3), r = i%(8*32*LDB3);
        int kc = r/(32*LDB3), q = r%(32*LDB3), kr = q/LDB3, n = q%LDB3;
        int k = kc*32 + kr;
        float v = (n < FML) ? W3[((size_t)nd*F0 + k)*FML + n] : 0.f;
        g_W3h[i] = __float2half_rn(v);
    }
}

// B chunk loader: linear 16B copies, one commit group. n16 = 16B units.
__device__ __forceinline__ void loadB(const __half* gh, int n16, uint32_t dst, int tid) {
    for (int j = tid; j < n16; j += STHR) cp16(dst + j*16, (const char*)gh + j*16);
    CP_COMMIT();
}

// flat k32 chunk prefetch: fj in [0,21)
__device__ __forceinline__ void prefetchFlat(int nd, int fj, const uint32_t* bufA, int tid) {
    uint32_t dst = bufA[fj & 1];
    if (fj < 5)       loadB(g_W1h + ((size_t)nd*5 + fj)*32*LDB,  1056, dst, tid);
    else if (fj < 13) loadB(g_W2h + ((size_t)nd*8 + (fj-5))*32*LDB, 1056, dst, tid);
    else              loadB(g_W3h + ((size_t)nd*8 + (fj-13))*32*LDB3, 288, dst, tid);
}

// compute one k16 sub-chunk, N=256 (warp tile 32x64); 2-pass (exact a = ah+al), pass-major
__device__ __forceinline__ void chunk256(uint32_t aHaddr, uint32_t aLaddr,
                                         uint32_t bBase, float (&acc)[2][8][4]) {
    uint32_t ah[2][4], al[2][4];
    ldsm4(aHaddr, ah[0]); ldsm4(aHaddr + 16*LDA*2, ah[1]);
    ldsm4(aLaddr, al[0]); ldsm4(aLaddr + 16*LDA*2, al[1]);
#pragma unroll
    for (int g = 0; g < 4; g++) {
        uint32_t bh[4];
        ldsm4t(bBase + g*32, bh);
#pragma unroll
        for (int mf = 0; mf < 2; mf++)
#pragma unroll
            for (int s = 0; s < 2; s++)
                mma16816(acc[mf][2*g + s], ah[mf], bh[2*s], bh[2*s+1]);
#pragma unroll
        for (int mf = 0; mf < 2; mf++)
#pragma unroll
            for (int s = 0; s < 2; s++)
                mma16816(acc[mf][2*g + s], al[mf], bh[2*s], bh[2*s+1]);
    }
}
// compute one k16 sub-chunk, N=64 (warp tile 32x16); 2-pass
__device__ __forceinline__ void chunk64(uint32_t aHaddr, uint32_t aLaddr,
                                        uint32_t bBase, float (&acc)[2][8][4]) {
    uint32_t ah[2][4], al[2][4], bh[4];
    ldsm4(aHaddr, ah[0]); ldsm4(aHaddr + 16*LDA*2, ah[1]);
    ldsm4(aLaddr, al[0]); ldsm4(aLaddr + 16*LDA*2, al[1]);
    ldsm4t(bBase, bh);
#pragma unroll
    for (int mf = 0; mf < 2; mf++)
#pragma unroll
        for (int s = 0; s < 2; s++)
            mma16816(acc[mf][s], ah[mf], bh[2*s], bh[2*s+1]);
#pragma unroll
    for (int mf = 0; mf < 2; mf++)
#pragma unroll
        for (int s = 0; s < 2; s++)
            mma16816(acc[mf][s], al[mf], bh[2*s], bh[2*s+1]);
}

// epilogue: relu(acc+bias) -> fp16 split -> store into A buffers; zero acc
__device__ __forceinline__ void epiA(float (&acc)[2][8][4], const float* sb,
                                     char* sm, int m0, int n0, int lane) {
#pragma unroll
    for (int mf = 0; mf < 2; mf++)
#pragma unroll
        for (int nf = 0; nf < 8; nf++) {
            int col = n0 + 8*nf + (lane & 3)*2;
            float bx = sb[col], by = sb[col+1];
            int r0 = m0 + 16*mf + (lane >> 2);
            float v00 = fmaxf(acc[mf][nf][0] + bx, 0.f);
            float v01 = fmaxf(acc[mf][nf][1] + by, 0.f);
            float v10 = fmaxf(acc[mf][nf][2] + bx, 0.f);
            float v11 = fmaxf(acc[mf][nf][3] + by, 0.f);
            __half h00 = __float2half_rn(v00), h01 = __float2half_rn(v01);
            __half h10 = __float2half_rn(v10), h11 = __float2half_rn(v11);
            *(__half2*)(sm + OFF_AH + ((size_t)r0*LDA + col)*2)     = __halves2half2(h00, h01);
            *(__half2*)(sm + OFF_AH + ((size_t)(r0+8)*LDA + col)*2) = __halves2half2(h10, h11);
            *(__half2*)(sm + OFF_AL + ((size_t)r0*LDA + col)*2) =
                __halves2half2(__float2half_rn(v00 - __half2float(h00)),
                               __float2half_rn(v01 - __half2float(h01)));
            *(__half2*)(sm + OFF_AL + ((size_t)(r0+8)*LDA + col)*2) =
                __halves2half2(__float2half_rn(v10 - __half2float(h10)),
                               __float2half_rn(v11 - __half2float(h11)));
            acc[mf][nf][0] = acc[mf][nf][1] = acc[mf][nf][2] = acc[mf][nf][3] = 0.f;
        }
}

// ---------------- one recurrent timestep (mma.sync, 2 CTAs/SM, k32 chunks) ----------------
__global__ void __launch_bounds__(STHR, 2) step3_kernel(
    const float* __restrict__ x,
    const float* __restrict__ b1, const float* __restrict__ b2,
    const float* __restrict__ b3, int t)
{
    extern __shared__ char sm[];
    const uint32_t smb = smem_to_u32(sm);

    const int tid = threadIdx.x, lane = tid & 31, wid = tid >> 5;
    const int mw = wid >> 2, nwc = wid & 3;      // warp grid 2x4
    const int m0 = mw * 32;
    const int n0 = nwc * 64;                     // N=256 layers
    const int n03 = nwc * 16;                    // N=64 layer
    const int nd = blockIdx.y;
    const int b0 = blockIdx.x * SM_M;
    const int rd = t & 1, wrp = rd ^ 1;
    const int p0 = c_par[nd][0], p1 = c_par[nd][1];

    float* sB1 = (float*)(sm + OFF_BIAS);
    float* sB2 = (float*)(sm + OFF_BIAS + 1024);
    float* sB3 = (float*)(sm + OFF_BIAS + 2048);
    if (tid < 256) { sB1[tid] = b1[nd*F0 + tid]; sB2[tid] = b2[nd*F0 + tid]; }
    if (tid < 64)  sB3[tid] = b3[nd*FML + tid];

    // per-thread ldmatrix base addresses
    const int rowoff = ((lane >> 3) & 1)*8 + (lane & 7);
    const int koffA  = (lane >> 4)*8;
    const uint32_t aH0 = smb + OFF_AH + (((uint32_t)(m0 + rowoff))*LDA + koffA)*2;
    const uint32_t aL0 = smb + OFF_AL + (((uint32_t)(m0 + rowoff))*LDA + koffA)*2;
    const uint32_t bRow = ((lane >> 3) & 1)*8 + (lane & 7);
    const uint32_t bCol = (uint32_t)(lane >> 4)*8;
    const uint32_t bOffL12 = (bRow*LDB + n0 + bCol)*2;
    const uint32_t bOffL3  = (bRow*LDB3 + n03 + bCol)*2;
    const uint32_t bufA[2] = { smb + OFF_B, smb + OFF_B + BUF_STRIDE };

    float acc[2][8][4];
#pragma unroll
    for (int a = 0; a < 2; a++)
#pragma unroll
        for (int b = 0; b < 8; b++)
#pragma unroll
            for (int c = 0; c < 4; c++) acc[a][b][c] = 0.f;

    // prefetch flat chunk 0
    prefetchFlat(nd, 0, bufA, tid);

    // gather L1 input A (fp16 split): cols 0..159 (130..159 zero)
    {
        const float* Sp0 = &g_state2[rd][p0][0][0];
        const float* Sp1 = &g_state2[rd][p1][0][0];
        for (int i = tid; i < SM_M*K1; i += STHR) {
            int r = i / K1, c = i % K1;
            float v = 0.f;
            if (c < 2)        v = x[(size_t)(b0 + r)*(NNODE*T_TOT) + (c ? p1 : p0)*T_TOT + t];
            else if (c < 66)  v = Sp0[(size_t)(b0 + r)*FML + (c - 2)];
            else if (c < 130) v = Sp1[(size_t)(b0 + r)*FML + (c - 66)];
            __half h = __float2half_rn(v);
            *(__half*)(sm + OFF_AH + ((size_t)r*LDA + c)*2) = h;
            *(__half*)(sm + OFF_AL + ((size_t)r*LDA + c)*2) = __float2half_rn(v - __half2float(h));
        }
    }

    int fj = 0;
    // ===== LAYER 1: 5 k32 chunks =====
    for (int kc = 0; kc < 5; kc++, fj++) {
        CP_WAIT0();
        __syncthreads();
        if (fj + 1 < NFLAT) prefetchFlat(nd, fj + 1, bufA, tid);
        uint32_t bb = bufA[fj & 1] + bOffL12;
        chunk256(aH0 + kc*64,      aL0 + kc*64,      bb,        acc);
        chunk256(aH0 + kc*64 + 32, aL0 + kc*64 + 32, bb + 8448, acc);
    }
    __syncthreads();
    epiA(acc, sB1, sm, m0, n0, lane);

    // ===== LAYER 2: 8 k32 chunks =====
    for (int kc = 0; kc < 8; kc++, fj++) {
        CP_WAIT0();
        __syncthreads();
        if (fj + 1 < NFLAT) prefetchFlat(nd, fj + 1, bufA, tid);
        uint32_t bb = bufA[fj & 1] + bOffL12;
        chunk256(aH0 + kc*64,      aL0 + kc*64,      bb,        acc);
        chunk256(aH0 + kc*64 + 32, aL0 + kc*64 + 32, bb + 8448, acc);
    }
    __syncthreads();
    epiA(acc, sB2, sm, m0, n0, lane);

    // ===== LAYER 3: 8 k32 chunks, N=64 =====
    for (int kc = 0; kc < 8; kc++, fj++) {
        CP_WAIT0();
        __syncthreads();
        if (fj + 1 < NFLAT) prefetchFlat(nd, fj + 1, bufA, tid);
        uint32_t bb = bufA[fj & 1] + bOffL3;
        chunk64(aH0 + kc*64,      aL0 + kc*64,      bb,        acc);
        chunk64(aH0 + kc*64 + 32, aL0 + kc*64 + 32, bb + 2304, acc);
    }

    // epilogue: state = tanh(acc + b3)
    float* gS = &g_state2[wrp][nd][0][0];
#pragma unroll
    for (int mf = 0; mf < 2; mf++)
#pragma unroll
        for (int nf = 0; nf < 2; nf++) {
            int col = n03 + 8*nf + (lane & 3)*2;
            float bx = sB3[col], by = sB3[col+1];
            int r0 = m0 + 16*mf + (lane >> 2);
            float2 o0, o1;
            o0.x = tanhf(acc[mf][nf][0] + bx);
            o0.y = tanhf(acc[mf][nf][1] + by);
            o1.x = tanhf(acc[mf][nf][2] + bx);
            o1.y = tanhf(acc[mf][nf][3] + by);
            *(float2*)(gS + (size_t)(b0 + r0)*FML + col)     = o0;
            *(float2*)(gS + (size_t)(b0 + r0 + 8)*FML + col) = o1;
        }
}

// ---------------- final head (SIMT) ----------------
__device__ __forceinline__ void ldw256(const float* __restrict__ gW, int K, int kbase,
                                       int tid, float4* pre) {
#pragma unroll
    for (int p = 0; p < 4; p++) {
        int q = p*NTHR + tid, row = q >> 6, c4 = q & 63;
        float4 v = make_float4(0.f, 0.f, 0.f, 0.f);
        if (kbase + row < K) v = *(const float4*)(gW + (size_t)(kbase+row)*256 + c4*4);
        pre[p] = v;
    }
}
__device__ __forceinline__ void stw256(float* sW, int tid, const float4* pre) {
#pragma unroll
    for (int p = 0; p < 4; p++) {
        int q = p*NTHR + tid, row = q >> 6, c4 = q & 63;
        *(float4*)(sW + row*256 + c4*4) = pre[p];
    }
}
__device__ __forceinline__ void gemm256(const float* __restrict__ sA, int lda,
                                        const float* __restrict__ gW, int K,
                                        const float* __restrict__ gb,
                                        float* __restrict__ sOut, int ldo,
                                        float* sW, int tid)
{
    const int tm = tid >> 5, tn = tid & 31;
    const int m0 = tm * 8, n0 = tn * 2;
    ull acc[8][4];
#pragma unroll
    for (int i = 0; i < 8; i++)
#pragma unroll
        for (int j = 0; j < 4; j++) acc[i][j] = 0ull;
    const int nt = (K + KT - 1) / KT;
    float4 pre[4];
    ldw256(gW, K, 0, tid, pre);
    stw256(sW, tid, pre);
    __syncthreads();
    for (int kt = 0; kt < nt; kt++) {
        if (kt + 1 < nt) ldw256(gW, K, (kt+1)*KT, tid, pre);
        const float* Wb = sW + (kt & 1) * (KT*256);
        const float* Arow = sA + m0*lda + kt*KT;
#pragma unroll
        for (int kk = 0; kk < KT; kk++) {
            const ull* bp = (const ull*)(Wb + kk*256 + n0);
            ull w0 = bp[0], w1 = bp[32], w2 = bp[64], w3 = bp[96];
#pragma unroll
            for (int i = 0; i < 8; i++) {
                float a = Arow[i*lda + kk];
                ull aa = pack2(a, a);
                acc[i][0] = fma2(aa, w0, acc[i][0]);
                acc[i][1] = fma2(aa, w1, acc[i][1]);
                acc[i][2] = fma2(aa, w2, acc[i][2]);
                acc[i][3] = fma2(aa, w3, acc[i][3]);
            }
        }
        if (kt + 1 < nt) stw256(sW + ((kt+1) & 1)*(KT*256), tid, pre);
        __syncthreads();
    }
    float2 bb[4];
#pragma unroll
    for (int j = 0; j < 4; j++) bb[j] = *(const float2*)(gb + n0 + 64*j);
#pragma unroll
    for (int i = 0; i < 8; i++)
#pragma unroll
        for (int j = 0; j < 4; j++) {
            float2 v = unpack2(acc[i][j]);
            v.x = fmaxf(v.x + bb[j].x, 0.f);
            v.y = fmaxf(v.y + bb[j].y, 0.f);
            *(float2*)(sOut + (m0+i)*ldo + n0 + 64*j) = v;
        }
}

__global__ __launch_bounds__(NTHR) void final1_kernel(
    const float* __restrict__ x,
    const float* __restrict__ Wo1, const float* __restrict__ bo1)
{
    extern __shared__ float smem[];
    float* sF = smem;
    float* sW = sF + TILE_B*LDF;
    const int tid = threadIdx.x;
    const int b0  = blockIdx.x * TILE_B;
    const float* st = &g_state2[0][0][0][0];

    for (int i = tid; i < TILE_B*320; i += NTHR) {
        int m = i / 320, c = i % 320;
        sF[m*LDF + NNODE + c] = st[((size_t)(c >> 6)*B_TOT + (b0+m))*FML + (c & 63)];
    }
    for (int i = tid; i < TILE_B*NNODE; i += NTHR) {
        int m = i / NNODE, nn = i % NNODE;
        sF[m*LDF + nn] = x[(size_t)(b0+m)*(NNODE*T_TOT) + nn*T_TOT + (T_TOT-1)];
    }
    for (int i = tid; i < TILE_B*(LDF-KFEAT); i += NTHR) {
        int m = i / (LDF-KFEAT), c = KFEAT + i % (LDF-KFEAT);
        sF[m*LDF + c] = 0.f;
    }
    __syncthreads();
    gemm256(sF, LDF, Wo1, KFEAT, bo1, sF, LDF, sW, tid);
    __syncthreads();
    for (int i = tid; i < TILE_B*F0; i += NTHR) {
        int m = i >> 8, c = i & 255;
        g_h[(size_t)(b0+m)*F0 + c] = sF[m*LDF + c];
    }
    float s = 0.f, q = 0.f;
    for (int m = 0; m < TILE_B; m++) {
        float v = sF[m*LDF + tid];
        s += v; q += v*v;
    }
    g_psum[blockIdx.x*F0 + tid] = s;
    g_psq [blockIdx.x*F0 + tid] = q;
}

__global__ void bn_kernel(const float* __restrict__ gamma, const float* __restrict__ beta) {
    int c = threadIdx.x;
    float s = 0.f, q = 0.f;
    for (int b = 0; b < (B_TOT/TILE_B); b++) { s += g_psum[b*F0 + c]; q += g_psq[b*F0 + c]; }
    float mu  = s * (1.f / B_TOT);
    float var = q * (1.f / B_TOT) - mu * mu;
    float sc = gamma[c] * rsqrtf(var + 1e-5f);
    g_scale[c] = sc;
    g_shift[c] = beta[c] - mu * sc;
}

__global__ __launch_bounds__(NTHR) void final2_kernel(
    const float* __restrict__ Wo2, const float* __restrict__ bo2, float* __restrict__ out)
{
    __shared__ float sw2[F0*7], sb2[7], ssc[F0], ssh[F0];
    const int tid = threadIdx.x;
    for (int i = tid; i < F0*7; i += NTHR) sw2[i] = Wo2[i];
    if (tid < 7) sb2[tid] = bo2[tid];
    ssc[tid] = g_scale[tid];
    ssh[tid] = g_shift[tid];
    __syncthreads();
    const int warp = tid >> 5, lane = tid & 31;
    for (int r = 0; r < 16; r++) {
        int b = blockIdx.x*128 + warp*16 + r;
        float a0=0,a1=0,a2=0,a3=0,a4=0,a5=0,a6=0;
        const float* hp = g_h + (size_t)b*F0;
#pragma unroll
        for (int kk = 0; kk < 8; kk++) {
            int k = kk*32 + lane;
            float hv = hp[k]*ssc[k] + ssh[k];
            const float* wrp2 = sw2 + k*7;
            a0 += hv*wrp2[0]; a1 += hv*wrp2[1]; a2 += hv*wrp2[2]; a3 += hv*wrp2[3];
            a4 += hv*wrp2[4]; a5 += hv*wrp2[5]; a6 += hv*wrp2[6];
        }
#pragma unroll
        for (int off = 16; off; off >>= 1) {
            a0 += __shfl_down_sync(0xffffffffu, a0, off);
            a1 += __shfl_down_sync(0xffffffffu, a1, off);
            a2 += __shfl_down_sync(0xffffffffu, a2, off);
            a3 += __shfl_down_sync(0xffffffffu, a3, off);
            a4 += __shfl_down_sync(0xffffffffu, a4, off);
            a5 += __shfl_down_sync(0xffffffffu, a5, off);
            a6 += __shfl_down_sync(0xffffffffu, a6, off);
        }
        if (lane == 0) {
            float l[7] = { a0+sb2[0], a1+sb2[1], a2+sb2[2], a3+sb2[3], a4+sb2[4], a5+sb2[5], a6+sb2[6] };
            float mx = l[0];
#pragma unroll
            for (int j = 1; j < 7; j++) mx = fmaxf(mx, l[j]);
            float e[7], se = 0.f;
#pragma unroll
            for (int j = 0; j < 7; j++) { e[j] = expf(l[j] - mx); se += e[j]; }
            float inv = 1.f / se;
#pragma unroll
            for (int j = 0; j < 7; j++) out[(size_t)b*7 + j] = e[j]*inv;
        }
    }
}

__global__ void zero_state_kernel() {
    size_t n = (size_t)NNODE*B_TOT*FML;
    float* p = &g_state2[0][0][0][0];
    for (size_t i = blockIdx.x*(size_t)blockDim.x + threadIdx.x; i < n;
         i += (size_t)gridDim.x*blockDim.x) p[i] = 0.f;
}

extern "C" void kernel_launch(void* const* d_in, const int* in_sizes, int n_in,
                              void* d_out, int out_size)
{
    (void)in_sizes; (void)n_in; (void)out_size;
    const float* x     = (const float*)d_in[0];
    const float* W1    = (const float*)d_in[1];
    const float* b1    = (const float*)d_in[2];
    const float* W2    = (const float*)d_in[3];
    const float* b2    = (const float*)d_in[4];
    const float* W3    = (const float*)d_in[5];
    const float* b3    = (const float*)d_in[6];
    const float* Wo1   = (const float*)d_in[7];
    const float* bo1   = (const float*)d_in[8];
    const float* gamma = (const float*)d_in[9];
    const float* beta  = (const float*)d_in[10];
    const float* Wo2   = (const float*)d_in[11];
    const float* bo2   = (const float*)d_in[12];
    float* out = (float*)d_out;

    const int F1_SMEM = (TILE_B*LDF + 2*KT*256) * (int)sizeof(float);
    cudaFuncSetAttribute(step3_kernel,  cudaFuncAttributeMaxDynamicSharedMemorySize, STEP_SMEM);
    cudaFuncSetAttribute(final1_kernel, cudaFuncAttributeMaxDynamicSharedMemorySize, F1_SMEM);

    prep_kernel<<<512, 256>>>(W1, W2, W3);
    zero_state_kernel<<<512, 256>>>();

    dim3 sgrid(B_TOT/SM_M, NNODE);   // (128, 5) = 640 CTAs, 2 per SM
    for (int t = 0; t < T_TOT; t++)
        step3_kernel<<<sgrid, STHR, STEP_SMEM>>>(x, b1, b2, b3, t);

    final1_kernel<<<B_TOT/TILE_B, NTHR, F1_SMEM>>>(x, Wo1, bo1);
    bn_kernel<<<1, F0>>>(gamma, beta);
    final2_kernel<<<64, NTHR>>>(Wo2, bo2, out);
}

// round 16
// speedup vs baseline: 2.6041x; 1.1611x over previous
#include <cuda_runtime.h>
#include <cuda_fp16.h>
#include <math.h>
#include <stdint.h>

typedef unsigned long long ull;

#define B_TOT 8192
#define T_TOT 128
#define NNODE 5
#define FML   64
#define F0    256
#define DIN   130
#define KFEAT 325
#define TILE_B 64
#define NTHR   256
#define KT     16
#define LDF    336

#define SM_M   64         // batch rows per step CTA (2 CTAs/SM)
#define STHR   512        // 16 warps: 4 M-bands x 4 N-cols (warp tile 16x64)
#define LDA    264        // A row pitch in halves (528B)
#define LDB    264        // B chunk row pitch (L1/L2)
#define LDB3   72         // B chunk row pitch (L3)
#define K1     160        // padded K of layer1 (5 x k32)
#define NFLAT  21         // flat k32 chunks: L1 5 + L2 8 + L3 8

__constant__ int c_par[NNODE][2] = {{3,4},{0,4},{0,1},{1,2},{2,3}};

// ---------------- device scratch ----------------
__device__ float g_state2[2][NNODE][B_TOT][FML];
__device__ float g_h[(size_t)B_TOT*F0];
__device__ float g_psum[(B_TOT/TILE_B)*F0];
__device__ float g_psq [(B_TOT/TILE_B)*F0];
__device__ float g_scale[F0], g_shift[F0];
// fp16 weights, k32-chunked [nd][chunk][32][pitch] (B plain fp16; accuracy via A hi/lo split)
__device__ __half g_W1h[5*5*32*LDB];
__device__ __half g_W2h[5*8*32*LDB];
__device__ __half g_W3h[5*8*32*LDB3];

// ---------------- f32x2 helpers (final head GEMM) ----------------
__device__ __forceinline__ ull fma2(ull a, ull b, ull c) {
    ull d; asm("fma.rn.f32x2 %0, %1, %2, %3;" : "=l"(d) : "l"(a), "l"(b), "l"(c)); return d;
}
__device__ __forceinline__ ull pack2(float x, float y) {
    ull d; asm("mov.b64 %0, {%1, %2};" : "=l"(d) : "f"(x), "f"(y)); return d;
}
__device__ __forceinline__ float2 unpack2(ull v) {
    float2 r; asm("mov.b64 {%0, %1}, %2;" : "=f"(r.x), "=f"(r.y) : "l"(v)); return r;
}

// ---------------- tensor-core primitives (baseline PTX, sm_80+) ----------------
__device__ __forceinline__ uint32_t smem_to_u32(const void* p) {
    uint32_t a; asm("{ .reg .u64 t; cvta.to.shared.u64 t, %1; cvt.u32.u64 %0, t; }" : "=r"(a) : "l"(p)); return a;
}
__device__ __forceinline__ void ldsm4(uint32_t a, uint32_t* r) {
    asm volatile("ldmatrix.sync.aligned.m8n8.x4.shared.b16 {%0,%1,%2,%3}, [%4];"
        : "=r"(r[0]), "=r"(r[1]), "=r"(r[2]), "=r"(r[3]) : "r"(a));
}
__device__ __forceinline__ void ldsm4t(uint32_t a, uint32_t* r) {
    asm volatile("ldmatrix.sync.aligned.m8n8.x4.trans.shared.b16 {%0,%1,%2,%3}, [%4];"
        : "=r"(r[0]), "=r"(r[1]), "=r"(r[2]), "=r"(r[3]) : "r"(a));
}
__device__ __forceinline__ void mma16816(float* c, const uint32_t* a, uint32_t b0, uint32_t b1) {
    asm volatile("mma.sync.aligned.m16n8k16.row.col.f32.f16.f16.f32 "
        "{%0,%1,%2,%3}, {%4,%5,%6,%7}, {%8,%9}, {%0,%1,%2,%3};"
        : "+f"(c[0]), "+f"(c[1]), "+f"(c[2]), "+f"(c[3])
        : "r"(a[0]), "r"(a[1]), "r"(a[2]), "r"(a[3]), "r"(b0), "r"(b1));
}
__device__ __forceinline__ void cp16(uint32_t dst, const void* src) {
    asm volatile("cp.async.cg.shared.global [%0], [%1], 16;" :: "r"(dst), "l"(src));
}
#define CP_COMMIT() asm volatile("cp.async.commit_group;" ::: "memory")
#define CP_WAIT0()  asm volatile("cp.async.wait_group 0;" ::: "memory")

// smem byte offsets (SM_M = 64, B fp16-only, k32 buffers)
#define OFF_AH   0
#define OFF_AL   33792                 // 64*264*2
#define OFF_B    67584                 // 2 buffers x 16896B
#define BUF_STRIDE 16896
#define OFF_BIAS 101376                // b1 (1024B) | b2 (1024B) | b3 (256B)
#define STEP_SMEM (101376 + 2304)

// ---------------- weight prep: transpose-to-k32-chunks + fp16 round ----------------
__global__ void prep_kernel(const float* __restrict__ W1, const float* __restrict__ W2,
                            const float* __restrict__ W3) {
    int i0 = blockIdx.x*blockDim.x + threadIdx.x, gs = gridDim.x*blockDim.x;
    for (int i = i0; i < 5*5*32*LDB; i += gs) {        // W1: [nd][5][32][264]
        int nd = i/(5*32*LDB), r = i%(5*32*LDB);
        int kc = r/(32*LDB), q = r%(32*LDB), kr = q/LDB, n = q%LDB;
        int k = kc*32 + kr;
        float v = (k < DIN && n < F0) ? W1[((size_t)nd*DIN + k)*F0 + n] : 0.f;
        g_W1h[i] = __float2half_rn(v);
    }
    for (int i = i0; i < 5*8*32*LDB; i += gs) {        // W2: [nd][8][32][264]
        int nd = i/(8*32*LDB), r = i%(8*32*LDB);
        int kc = r/(32*LDB), q = r%(32*LDB), kr = q/LDB, n = q%LDB;
        int k = kc*32 + kr;
        float v = (n < F0) ? W2[((size_t)nd*F0 + k)*F0 + n] : 0.f;
        g_W2h[i] = __float2half_rn(v);
    }
    for (int i = i0; i < 5*8*32*LDB3; i += gs) {       // W3: [nd][8][32][72]
        int nd = i/(8*32*LDB3), r = i%(8*32*LDB3);
        int kc = r/(32*LDB3), q = r%(32*LDB3), kr = q/LDB3, n = q%LDB3;
        int k = kc*32 + kr;
        float v = (n < FML) ? W3[((size_t)nd*F0 + k)*FML + n] : 0.f;
        g_W3h[i] = __float2half_rn(v);
    }
}

// B chunk loader: linear 16B copies, one commit group. n16 = 16B units.
__device__ __forceinline__ void loadB(const __half* gh, int n16, uint32_t dst, int tid) {
    for (int j = tid; j < n16; j += STHR) cp16(dst + j*16, (const char*)gh + j*16);
    CP_COMMIT();
}

// flat k32 chunk prefetch: fj in [0,21)
__device__ __forceinline__ void prefetchFlat(int nd, int fj, const uint32_t* bufA, int tid) {
    uint32_t dst = bufA[fj & 1];
    if (fj < 5)       loadB(g_W1h + ((size_t)nd*5 + fj)*32*LDB,  1056, dst, tid);
    else if (fj < 13) loadB(g_W2h + ((size_t)nd*8 + (fj-5))*32*LDB, 1056, dst, tid);
    else              loadB(g_W3h + ((size_t)nd*8 + (fj-13))*32*LDB3, 288, dst, tid);
}

// compute one k16 sub-chunk, N=256 (warp tile 16x64); 2-pass (exact a = ah+al), pass-major
__device__ __forceinline__ void chunk256(uint32_t aHaddr, uint32_t aLaddr,
                                         uint32_t bBase, float (&acc)[8][4]) {
    uint32_t ah[4], al[4];
    ldsm4(aHaddr, ah);
    ldsm4(aLaddr, al);
#pragma unroll
    for (int g = 0; g < 4; g++) {
        uint32_t bh[4];
        ldsm4t(bBase + g*32, bh);
#pragma unroll
        for (int s = 0; s < 2; s++)
            mma16816(acc[2*g + s], ah, bh[2*s], bh[2*s+1]);
#pragma unroll
        for (int s = 0; s < 2; s++)
            mma16816(acc[2*g + s], al, bh[2*s], bh[2*s+1]);
    }
}
// compute one k16 sub-chunk, N=64 (warp tile 16x16); 2-pass
__device__ __forceinline__ void chunk64(uint32_t aHaddr, uint32_t aLaddr,
                                        uint32_t bBase, float (&acc)[8][4]) {
    uint32_t ah[4], al[4], bh[4];
    ldsm4(aHaddr, ah);
    ldsm4(aLaddr, al);
    ldsm4t(bBase, bh);
#pragma unroll
    for (int s = 0; s < 2; s++)
        mma16816(acc[s], ah, bh[2*s], bh[2*s+1]);
#pragma unroll
    for (int s = 0; s < 2; s++)
        mma16816(acc[s], al, bh[2*s], bh[2*s+1]);
}

// epilogue: relu(acc+bias) -> fp16 split -> store into A buffers; zero acc
__device__ __forceinline__ void epiA(float (&acc)[8][4], const float* sb,
                                     char* sm, int m0, int n0, int lane) {
#pragma unroll
    for (int nf = 0; nf < 8; nf++) {
        int col = n0 + 8*nf + (lane & 3)*2;
        float bx = sb[col], by = sb[col+1];
        int r0 = m0 + (lane >> 2);
        float v00 = fmaxf(acc[nf][0] + bx, 0.f);
        float v01 = fmaxf(acc[nf][1] + by, 0.f);
        float v10 = fmaxf(acc[nf][2] + bx, 0.f);
        float v11 = fmaxf(acc[nf][3] + by, 0.f);
        __half h00 = __float2half_rn(v00), h01 = __float2half_rn(v01);
        __half h10 = __float2half_rn(v10), h11 = __float2half_rn(v11);
        *(__half2*)(sm + OFF_AH + ((size_t)r0*LDA + col)*2)     = __halves2half2(h00, h01);
        *(__half2*)(sm + OFF_AH + ((size_t)(r0+8)*LDA + col)*2) = __halves2half2(h10, h11);
        *(__half2*)(sm + OFF_AL + ((size_t)r0*LDA + col)*2) =
            __halves2half2(__float2half_rn(v00 - __half2float(h00)),
                           __float2half_rn(v01 - __half2float(h01)));
        *(__half2*)(sm + OFF_AL + ((size_t)(r0+8)*LDA + col)*2) =
            __halves2half2(__float2half_rn(v10 - __half2float(h10)),
                           __float2half_rn(v11 - __half2float(h11)));
        acc[nf][0] = acc[nf][1] = acc[nf][2] = acc[nf][3] = 0.f;
    }
}

// ---------------- one recurrent timestep (mma.sync, 2 CTAs/SM, 16 warps/CTA) ----------------
__global__ void __launch_bounds__(STHR, 2) step3_kernel(
    const float* __restrict__ x,
    const float* __restrict__ b1, const float* __restrict__ b2,
    const float* __restrict__ b3, int t)
{
    extern __shared__ char sm[];
    const uint32_t smb = smem_to_u32(sm);

    const int tid = threadIdx.x, lane = tid & 31, wid = tid >> 5;
    const int mw = wid >> 2, nwc = wid & 3;      // warp grid 4x4
    const int m0 = mw * 16;                      // 16-row warp band
    const int n0 = nwc * 64;                     // N=256 layers
    const int n03 = nwc * 16;                    // N=64 layer
    const int nd = blockIdx.y;
    const int b0 = blockIdx.x * SM_M;
    const int rd = t & 1, wrp = rd ^ 1;
    const int p0 = c_par[nd][0], p1 = c_par[nd][1];

    float* sB1 = (float*)(sm + OFF_BIAS);
    float* sB2 = (float*)(sm + OFF_BIAS + 1024);
    float* sB3 = (float*)(sm + OFF_BIAS + 2048);
    if (tid < 256) { sB1[tid] = b1[nd*F0 + tid]; sB2[tid] = b2[nd*F0 + tid]; }
    if (tid < 64)  sB3[tid] = b3[nd*FML + tid];

    // per-thread ldmatrix base addresses (row = lane&15, k-col = (lane>>4)*8)
    const int rowoff = ((lane >> 3) & 1)*8 + (lane & 7);
    const int koffA  = (lane >> 4)*8;
    const uint32_t aH0 = smb + OFF_AH + (((uint32_t)(m0 + rowoff))*LDA + koffA)*2;
    const uint32_t aL0 = smb + OFF_AL + (((uint32_t)(m0 + rowoff))*LDA + koffA)*2;
    const uint32_t bRow = ((lane >> 3) & 1)*8 + (lane & 7);
    const uint32_t bCol = (uint32_t)(lane >> 4)*8;
    const uint32_t bOffL12 = (bRow*LDB + n0 + bCol)*2;
    const uint32_t bOffL3  = (bRow*LDB3 + n03 + bCol)*2;
    const uint32_t bufA[2] = { smb + OFF_B, smb + OFF_B + BUF_STRIDE };

    float acc[8][4];
#pragma unroll
    for (int b = 0; b < 8; b++)
#pragma unroll
        for (int c = 0; c < 4; c++) acc[b][c] = 0.f;

    // prefetch flat chunk 0
    prefetchFlat(nd, 0, bufA, tid);

    // gather L1 input A (fp16 split): cols 0..159 (130..159 zero)
    {
        const float* Sp0 = &g_state2[rd][p0][0][0];
        const float* Sp1 = &g_state2[rd][p1][0][0];
        for (int i = tid; i < SM_M*K1; i += STHR) {
            int r = i / K1, c = i % K1;
            float v = 0.f;
            if (c < 2)        v = x[(size_t)(b0 + r)*(NNODE*T_TOT) + (c ? p1 : p0)*T_TOT + t];
            else if (c < 66)  v = Sp0[(size_t)(b0 + r)*FML + (c - 2)];
            else if (c < 130) v = Sp1[(size_t)(b0 + r)*FML + (c - 66)];
            __half h = __float2half_rn(v);
            *(__half*)(sm + OFF_AH + ((size_t)r*LDA + c)*2) = h;
            *(__half*)(sm + OFF_AL + ((size_t)r*LDA + c)*2) = __float2half_rn(v - __half2float(h));
        }
    }

    int fj = 0;
    // ===== LAYER 1: 5 k32 chunks =====
    for (int kc = 0; kc < 5; kc++, fj++) {
        CP_WAIT0();
        __syncthreads();
        if (fj + 1 < NFLAT) prefetchFlat(nd, fj + 1, bufA, tid);
        uint32_t bb = bufA[fj & 1] + bOffL12;
        chunk256(aH0 + kc*64,      aL0 + kc*64,      bb,        acc);
        chunk256(aH0 + kc*64 + 32, aL0 + kc*64 + 32, bb + 8448, acc);
    }
    __syncthreads();
    epiA(acc, sB1, sm, m0, n0, lane);

    // ===== LAYER 2: 8 k32 chunks =====
    for (int kc = 0; kc < 8; kc++, fj++) {
        CP_WAIT0();
        __syncthreads();
        if (fj + 1 < NFLAT) prefetchFlat(nd, fj + 1, bufA, tid);
        uint32_t bb = bufA[fj & 1] + bOffL12;
        chunk256(aH0 + kc*64,      aL0 + kc*64,      bb,        acc);
        chunk256(aH0 + kc*64 + 32, aL0 + kc*64 + 32, bb + 8448, acc);
    }
    __syncthreads();
    epiA(acc, sB2, sm, m0, n0, lane);

    // ===== LAYER 3: 8 k32 chunks, N=64 =====
    for (int kc = 0; kc < 8; kc++, fj++) {
        CP_WAIT0();
        __syncthreads();
        if (fj + 1 < NFLAT) prefetchFlat(nd, fj + 1, bufA, tid);
        uint32_t bb = bufA[fj & 1] + bOffL3;
        chunk64(aH0 + kc*64,      aL0 + kc*64,      bb,        acc);
        chunk64(aH0 + kc*64 + 32, aL0 + kc*64 + 32, bb + 2304, acc);
    }

    // epilogue: state = tanh(acc + b3)
    float* gS = &g_state2[wrp][nd][0][0];
#pragma unroll
    for (int nf = 0; nf < 2; nf++) {
        int col = n03 + 8*nf + (lane & 3)*2;
        float bx = sB3[col], by = sB3[col+1];
        int r0 = m0 + (lane >> 2);
        float2 o0, o1;
        o0.x = tanhf(acc[nf][0] + bx);
        o0.y = tanhf(acc[nf][1] + by);
        o1.x = tanhf(acc[nf][2] + bx);
        o1.y = tanhf(acc[nf][3] + by);
        *(float2*)(gS + (size_t)(b0 + r0)*FML + col)     = o0;
        *(float2*)(gS + (size_t)(b0 + r0 + 8)*FML + col) = o1;
    }
}

// ---------------- final head (SIMT) ----------------
__device__ __forceinline__ void ldw256(const float* __restrict__ gW, int K, int kbase,
                                       int tid, float4* pre) {
#pragma unroll
    for (int p = 0; p < 4; p++) {
        int q = p*NTHR + tid, row = q >> 6, c4 = q & 63;
        float4 v = make_float4(0.f, 0.f, 0.f, 0.f);
        if (kbase + row < K) v = *(const float4*)(gW + (size_t)(kbase+row)*256 + c4*4);
        pre[p] = v;
    }
}
__device__ __forceinline__ void stw256(float* sW, int tid, const float4* pre) {
#pragma unroll
    for (int p = 0; p < 4; p++) {
        int q = p*NTHR + tid, row = q >> 6, c4 = q & 63;
        *(float4*)(sW + row*256 + c4*4) = pre[p];
    }
}
__device__ __forceinline__ void gemm256(const float* __restrict__ sA, int lda,
                                        const float* __restrict__ gW, int K,
                                        const float* __restrict__ gb,
                                        float* __restrict__ sOut, int ldo,
                                        float* sW, int tid)
{
    const int tm = tid >> 5, tn = tid & 31;
    const int m0 = tm * 8, n0 = tn * 2;
    ull acc[8][4];
#pragma unroll
    for (int i = 0; i < 8; i++)
#pragma unroll
        for (int j = 0; j < 4; j++) acc[i][j] = 0ull;
    const int nt = (K + KT - 1) / KT;
    float4 pre[4];
    ldw256(gW, K, 0, tid, pre);
    stw256(sW, tid, pre);
    __syncthreads();
    for (int kt = 0; kt < nt; kt++) {
        if (kt + 1 < nt) ldw256(gW, K, (kt+1)*KT, tid, pre);
        const float* Wb = sW + (kt & 1) * (KT*256);
        const float* Arow = sA + m0*lda + kt*KT;
#pragma unroll
        for (int kk = 0; kk < KT; kk++) {
            const ull* bp = (const ull*)(Wb + kk*256 + n0);
            ull w0 = bp[0], w1 = bp[32], w2 = bp[64], w3 = bp[96];
#pragma unroll
            for (int i = 0; i < 8; i++) {
                float a = Arow[i*lda + kk];
                ull aa = pack2(a, a);
                acc[i][0] = fma2(aa, w0, acc[i][0]);
                acc[i][1] = fma2(aa, w1, acc[i][1]);
                acc[i][2] = fma2(aa, w2, acc[i][2]);
                acc[i][3] = fma2(aa, w3, acc[i][3]);
            }
        }
        if (kt + 1 < nt) stw256(sW + ((kt+1) & 1)*(KT*256), tid, pre);
        __syncthreads();
    }
    float2 bb[4];
#pragma unroll
    for (int j = 0; j < 4; j++) bb[j] = *(const float2*)(gb + n0 + 64*j);
#pragma unroll
    for (int i = 0; i < 8; i++)
#pragma unroll
        for (int j = 0; j < 4; j++) {
            float2 v = unpack2(acc[i][j]);
            v.x = fmaxf(v.x + bb[j].x, 0.f);
            v.y = fmaxf(v.y + bb[j].y, 0.f);
            *(float2*)(sOut + (m0+i)*ldo + n0 + 64*j) = v;
        }
}

__global__ __launch_bounds__(NTHR) void final1_kernel(
    const float* __restrict__ x,
    const float* __restrict__ Wo1, const float* __restrict__ bo1)
{
    extern __shared__ float smem[];
    float* sF = smem;
    float* sW = sF + TILE_B*LDF;
    const int tid = threadIdx.x;
    const int b0  = blockIdx.x * TILE_B;
    const float* st = &g_state2[0][0][0][0];

    for (int i = tid; i < TILE_B*320; i += NTHR) {
        int m = i / 320, c = i % 320;
        sF[m*LDF + NNODE + c] = st[((size_t)(c >> 6)*B_TOT + (b0+m))*FML + (c & 63)];
    }
    for (int i = tid; i < TILE_B*NNODE; i += NTHR) {
        int m = i / NNODE, nn = i % NNODE;
        sF[m*LDF + nn] = x[(size_t)(b0+m)*(NNODE*T_TOT) + nn*T_TOT + (T_TOT-1)];
    }
    for (int i = tid; i < TILE_B*(LDF-KFEAT); i += NTHR) {
        int m = i / (LDF-KFEAT), c = KFEAT + i % (LDF-KFEAT);
        sF[m*LDF + c] = 0.f;
    }
    __syncthreads();
    gemm256(sF, LDF, Wo1, KFEAT, bo1, sF, LDF, sW, tid);
    __syncthreads();
    for (int i = tid; i < TILE_B*F0; i += NTHR) {
        int m = i >> 8, c = i & 255;
        g_h[(size_t)(b0+m)*F0 + c] = sF[m*LDF + c];
    }
    float s = 0.f, q = 0.f;
    for (int m = 0; m < TILE_B; m++) {
        float v = sF[m*LDF + tid];
        s += v; q += v*v;
    }
    g_psum[blockIdx.x*F0 + tid] = s;
    g_psq [blockIdx.x*F0 + tid] = q;
}

__global__ void bn_kernel(const float* __restrict__ gamma, const float* __restrict__ beta) {
    int c = threadIdx.x;
    float s = 0.f, q = 0.f;
    for (int b = 0; b < (B_TOT/TILE_B); b++) { s += g_psum[b*F0 + c]; q += g_psq[b*F0 + c]; }
    float mu  = s * (1.f / B_TOT);
    float var = q * (1.f / B_TOT) - mu * mu;
    float sc = gamma[c] * rsqrtf(var + 1e-5f);
    g_scale[c] = sc;
    g_shift[c] = beta[c] - mu * sc;
}

__global__ __launch_bounds__(NTHR) void final2_kernel(
    const float* __restrict__ Wo2, const float* __restrict__ bo2, float* __restrict__ out)
{
    __shared__ float sw2[F0*7], sb2[7], ssc[F0], ssh[F0];
    const int tid = threadIdx.x;
    for (int i = tid; i < F0*7; i += NTHR) sw2[i] = Wo2[i];
    if (tid < 7) sb2[tid] = bo2[tid];
    ssc[tid] = g_scale[tid];
    ssh[tid] = g_shift[tid];
    __syncthreads();
    const int warp = tid >> 5, lane = tid & 31;
    for (int r = 0; r < 16; r++) {
        int b = blockIdx.x*128 + warp*16 + r;
        float a0=0,a1=0,a2=0,a3=0,a4=0,a5=0,a6=0;
        const float* hp = g_h + (size_t)b*F0;
#pragma unroll
        for (int kk = 0; kk < 8; kk++) {
            int k = kk*32 + lane;
            float hv = hp[k]*ssc[k] + ssh[k];
            const float* wrp2 = sw2 + k*7;
            a0 += hv*wrp2[0]; a1 += hv*wrp2[1]; a2 += hv*wrp2[2]; a3 += hv*wrp2[3];
            a4 += hv*wrp2[4]; a5 += hv*wrp2[5]; a6 += hv*wrp2[6];
        }
#pragma unroll
        for (int off = 16; off; off >>= 1) {
            a0 += __shfl_down_sync(0xffffffffu, a0, off);
            a1 += __shfl_down_sync(0xffffffffu, a1, off);
            a2 += __shfl_down_sync(0xffffffffu, a2, off);
            a3 += __shfl_down_sync(0xffffffffu, a3, off);
            a4 += __shfl_down_sync(0xffffffffu, a4, off);
            a5 += __shfl_down_sync(0xffffffffu, a5, off);
            a6 += __shfl_down_sync(0xffffffffu, a6, off);
        }
        if (lane == 0) {
            float l[7] = { a0+sb2[0], a1+sb2[1], a2+sb2[2], a3+sb2[3], a4+sb2[4], a5+sb2[5], a6+sb2[6] };
            float mx = l[0];
#pragma unroll
            for (int j = 1; j < 7; j++) mx = fmaxf(mx, l[j]);
            float e[7], se = 0.f;
#pragma unroll
            for (int j = 0; j < 7; j++) { e[j] = expf(l[j] - mx); se += e[j]; }
            float inv = 1.f / se;
#pragma unroll
            for (int j = 0; j < 7; j++) out[(size_t)b*7 + j] = e[j]*inv;
        }
    }
}

__global__ void zero_state_kernel() {
    size_t n = (size_t)NNODE*B_TOT*FML;
    float* p = &g_state2[0][0][0][0];
    for (size_t i = blockIdx.x*(size_t)blockDim.x + threadIdx.x; i < n;
         i += (size_t)gridDim.x*blockDim.x) p[i] = 0.f;
}

extern "C" void kernel_launch(void* const* d_in, const int* in_sizes, int n_in,
                              void* d_out, int out_size)
{
    (void)in_sizes; (void)n_in; (void)out_size;
    const float* x     = (const float*)d_in[0];
    const float* W1    = (const float*)d_in[1];
    const float* b1    = (const float*)d_in[2];
    const float* W2    = (const float*)d_in[3];
    const float* b2    = (const float*)d_in[4];
    const float* W3    = (const float*)d_in[5];
    const float* b3    = (const float*)d_in[6];
    const float* Wo1   = (const float*)d_in[7];
    const float* bo1   = (const float*)d_in[8];
    const float* gamma = (const float*)d_in[9];
    const float* beta  = (const float*)d_in[10];
    const float* Wo2   = (const float*)d_in[11];
    const float* bo2   = (const float*)d_in[12];
    float* out = (float*)d_out;

    const int F1_SMEM = (TILE_B*LDF + 2*KT*256) * (int)sizeof(float);
    cudaFuncSetAttribute(step3_kernel,  cudaFuncAttributeMaxDynamicSharedMemorySize, STEP_SMEM);
    cudaFuncSetAttribute(final1_kernel, cudaFuncAttributeMaxDynamicSharedMemorySize, F1_SMEM);

    prep_kernel<<<512, 256>>>(W1, W2, W3);
    zero_state_kernel<<<512, 256>>>();

    dim3 sgrid(B_TOT/SM_M, NNODE);   // (128, 5) = 640 CTAs, 2 per SM
    for (int t = 0; t < T_TOT; t++)
        step3_kernel<<<sgrid, STHR, STEP_SMEM>>>(x, b1, b2, b3, t);

    final1_kernel<<<B_TOT/TILE_B, NTHR, F1_SMEM>>>(x, Wo1, bo1);
    bn_kernel<<<1, F0>>>(gamma, beta);
    final2_kernel<<<64, NTHR>>>(Wo2, bo2, out);
}

// round 17
// speedup vs baseline: 2.9778x; 1.1435x over previous
#include <cuda_runtime.h>
#include <cuda_fp16.h>
#include <math.h>
#include <stdint.h>

typedef unsigned long long ull;

#define B_TOT 8192
#define T_TOT 128
#define NNODE 5
#define FML   64
#define F0    256
#define DIN   130
#define KFEAT 325
#define TILE_B 64
#define NTHR   256
#define KT     16
#define LDF    336

#define SM_M   64         // batch rows per step CTA (2 CTAs/SM)
#define STHR   512        // 16 warps: 4 M-bands x 4 N-cols (warp tile 16x64)
#define LDA    264        // A row pitch in halves (528B)
#define LDB    264        // B chunk row pitch (L1/L2)
#define LDB3   72         // B chunk row pitch (L3)
#define K1     160        // padded K of layer1 (5 x k32)
#define NFLAT  17         // flat chunks: L1 5 (k32) + L2 8 (k32) + L3 4 (k64)

__constant__ int c_par[NNODE][2] = {{3,4},{0,4},{0,1},{1,2},{2,3}};

// ---------------- device scratch ----------------
__device__ float g_state2[2][NNODE][B_TOT][FML];
__device__ float g_h[(size_t)B_TOT*F0];
__device__ float g_psum[(B_TOT/TILE_B)*F0];
__device__ float g_psq [(B_TOT/TILE_B)*F0];
__device__ float g_scale[F0], g_shift[F0];
// fp16 weights (B plain fp16; accuracy via A hi/lo split in L1 + fp32 accum)
__device__ __half g_W1h[5*5*32*LDB];     // k32 chunks
__device__ __half g_W2h[5*8*32*LDB];     // k32 chunks
__device__ __half g_W3h[5*4*64*LDB3];    // k64 chunks

// ---------------- f32x2 helpers (final head GEMM) ----------------
__device__ __forceinline__ ull fma2(ull a, ull b, ull c) {
    ull d; asm("fma.rn.f32x2 %0, %1, %2, %3;" : "=l"(d) : "l"(a), "l"(b), "l"(c)); return d;
}
__device__ __forceinline__ ull pack2(float x, float y) {
    ull d; asm("mov.b64 %0, {%1, %2};" : "=l"(d) : "f"(x), "f"(y)); return d;
}
__device__ __forceinline__ float2 unpack2(ull v) {
    float2 r; asm("mov.b64 {%0, %1}, %2;" : "=f"(r.x), "=f"(r.y) : "l"(v)); return r;
}

// ---------------- tensor-core primitives (baseline PTX, sm_80+) ----------------
__device__ __forceinline__ uint32_t smem_to_u32(const void* p) {
    uint32_t a; asm("{ .reg .u64 t; cvta.to.shared.u64 t, %1; cvt.u32.u64 %0, t; }" : "=r"(a) : "l"(p)); return a;
}
__device__ __forceinline__ void ldsm4(uint32_t a, uint32_t* r) {
    asm volatile("ldmatrix.sync.aligned.m8n8.x4.shared.b16 {%0,%1,%2,%3}, [%4];"
        : "=r"(r[0]), "=r"(r[1]), "=r"(r[2]), "=r"(r[3]) : "r"(a));
}
__device__ __forceinline__ void ldsm4t(uint32_t a, uint32_t* r) {
    asm volatile("ldmatrix.sync.aligned.m8n8.x4.trans.shared.b16 {%0,%1,%2,%3}, [%4];"
        : "=r"(r[0]), "=r"(r[1]), "=r"(r[2]), "=r"(r[3]) : "r"(a));
}
__device__ __forceinline__ void mma16816(float* c, const uint32_t* a, uint32_t b0, uint32_t b1) {
    asm volatile("mma.sync.aligned.m16n8k16.row.col.f32.f16.f16.f32 "
        "{%0,%1,%2,%3}, {%4,%5,%6,%7}, {%8,%9}, {%0,%1,%2,%3};"
        : "+f"(c[0]), "+f"(c[1]), "+f"(c[2]), "+f"(c[3])
        : "r"(a[0]), "r"(a[1]), "r"(a[2]), "r"(a[3]), "r"(b0), "r"(b1));
}
__device__ __forceinline__ void cp16(uint32_t dst, const void* src) {
    asm volatile("cp.async.cg.shared.global [%0], [%1], 16;" :: "r"(dst), "l"(src));
}
#define CP_COMMIT() asm volatile("cp.async.commit_group;" ::: "memory")
#define CP_WAIT0()  asm volatile("cp.async.wait_group 0;" ::: "memory")

// smem byte offsets (SM_M = 64, B fp16-only, k32/k64 buffers)
#define OFF_AH   0
#define OFF_AL   33792                 // 64*264*2
#define OFF_B    67584                 // 2 buffers x 16896B
#define BUF_STRIDE 16896
#define OFF_BIAS 101376                // b1 (1024B) | b2 (1024B) | b3 (256B)
#define STEP_SMEM (101376 + 2304)

// ---------------- weight prep: transpose-to-chunks + fp16 round ----------------
__global__ void prep_kernel(const float* __restrict__ W1, const float* __restrict__ W2,
                            const float* __restrict__ W3) {
    int i0 = blockIdx.x*blockDim.x + threadIdx.x, gs = gridDim.x*blockDim.x;
    for (int i = i0; i < 5*5*32*LDB; i += gs) {        // W1: [nd][5][32][264]
        int nd = i/(5*32*LDB), r = i%(5*32*LDB);
        int kc = r/(32*LDB), q = r%(32*LDB), kr = q/LDB, n = q%LDB;
        int k = kc*32 + kr;
        float v = (k < DIN && n < F0) ? W1[((size_t)nd*DIN + k)*F0 + n] : 0.f;
        g_W1h[i] = __float2half_rn(v);
    }
    for (int i = i0; i < 5*8*32*LDB; i += gs) {        // W2: [nd][8][32][264]
        int nd = i/(8*32*LDB), r = i%(8*32*LDB);
        int kc = r/(32*LDB), q = r%(32*LDB), kr = q/LDB, n = q%LDB;
        int k = kc*32 + kr;
        float v = (n < F0) ? W2[((size_t)nd*F0 + k)*F0 + n] : 0.f;
        g_W2h[i] = __float2half_rn(v);
    }
    for (int i = i0; i < 5*4*64*LDB3; i += gs) {       // W3: [nd][4][64][72]
        int nd = i/(4*64*LDB3), r = i%(4*64*LDB3);
        int kc = r/(64*LDB3), q = r%(64*LDB3), kr = q/LDB3, n = q%LDB3;
        int k = kc*64 + kr;
        float v = (n < FML) ? W3[((size_t)nd*F0 + k)*FML + n] : 0.f;
        g_W3h[i] = __float2half_rn(v);
    }
}

// B chunk loader: linear 16B copies, one commit group. n16 = 16B units.
__device__ __forceinline__ void loadB(const __half* gh, int n16, uint32_t dst, int tid) {
    for (int j = tid; j < n16; j += STHR) cp16(dst + j*16, (const char*)gh + j*16);
    CP_COMMIT();
}

// flat chunk prefetch: fj in [0,17)
__device__ __forceinline__ void prefetchFlat(int nd, int fj, const uint32_t* bufA, int tid) {
    uint32_t dst = bufA[fj & 1];
    if (fj < 5)       loadB(g_W1h + ((size_t)nd*5 + fj)*32*LDB,  1056, dst, tid);
    else if (fj < 13) loadB(g_W2h + ((size_t)nd*8 + (fj-5))*32*LDB, 1056, dst, tid);
    else              loadB(g_W3h + ((size_t)nd*4 + (fj-13))*64*LDB3, 576, dst, tid);
}

// k16 sub-chunk, N=256, 2-pass (L1: exact a = ah+al), pass-major
__device__ __forceinline__ void chunk256_2p(uint32_t aHaddr, uint32_t aLaddr,
                                            uint32_t bBase, float (&acc)[8][4]) {
    uint32_t ah[4], al[4];
    ldsm4(aHaddr, ah);
    ldsm4(aLaddr, al);
#pragma unroll
    for (int g = 0; g < 4; g++) {
        uint32_t bh[4];
        ldsm4t(bBase + g*32, bh);
#pragma unroll
        for (int s = 0; s < 2; s++)
            mma16816(acc[2*g + s], ah, bh[2*s], bh[2*s+1]);
#pragma unroll
        for (int s = 0; s < 2; s++)
            mma16816(acc[2*g + s], al, bh[2*s], bh[2*s+1]);
    }
}
// k16 sub-chunk, N=256, 1-pass (L2: fp16 activations)
__device__ __forceinline__ void chunk256_1p(uint32_t aHaddr, uint32_t bBase,
                                            float (&acc)[8][4]) {
    uint32_t ah[4];
    ldsm4(aHaddr, ah);
#pragma unroll
    for (int g = 0; g < 4; g++) {
        uint32_t bh[4];
        ldsm4t(bBase + g*32, bh);
#pragma unroll
        for (int s = 0; s < 2; s++)
            mma16816(acc[2*g + s], ah, bh[2*s], bh[2*s+1]);
    }
}
// k16 sub-chunk, N=64, 1-pass (L3)
__device__ __forceinline__ void chunk64_1p(uint32_t aHaddr, uint32_t bBase,
                                           float (&acc)[8][4]) {
    uint32_t ah[4], bh[4];
    ldsm4(aHaddr, ah);
    ldsm4t(bBase, bh);
#pragma unroll
    for (int s = 0; s < 2; s++)
        mma16816(acc[s], ah, bh[2*s], bh[2*s+1]);
}

// epilogue: relu(acc+bias) -> fp16 -> store into A-hi buffer; zero acc
// (lo not needed: downstream layers use 1-pass A)
__device__ __forceinline__ void epiA(float (&acc)[8][4], const float* sb,
                                     char* sm, int m0, int n0, int lane) {
#pragma unroll
    for (int nf = 0; nf < 8; nf++) {
        int col = n0 + 8*nf + (lane & 3)*2;
        float bx = sb[col], by = sb[col+1];
        int r0 = m0 + (lane >> 2);
        float v00 = fmaxf(acc[nf][0] + bx, 0.f);
        float v01 = fmaxf(acc[nf][1] + by, 0.f);
        float v10 = fmaxf(acc[nf][2] + bx, 0.f);
        float v11 = fmaxf(acc[nf][3] + by, 0.f);
        *(__half2*)(sm + OFF_AH + ((size_t)r0*LDA + col)*2) =
            __halves2half2(__float2half_rn(v00), __float2half_rn(v01));
        *(__half2*)(sm + OFF_AH + ((size_t)(r0+8)*LDA + col)*2) =
            __halves2half2(__float2half_rn(v10), __float2half_rn(v11));
        acc[nf][0] = acc[nf][1] = acc[nf][2] = acc[nf][3] = 0.f;
    }
}

// ---------------- one recurrent timestep (mma.sync, 2 CTAs/SM, 16 warps/CTA) ----------------
__global__ void __launch_bounds__(STHR, 2) step3_kernel(
    const float* __restrict__ x,
    const float* __restrict__ b1, const float* __restrict__ b2,
    const float* __restrict__ b3, int t)
{
    extern __shared__ char sm[];
    const uint32_t smb = smem_to_u32(sm);

    const int tid = threadIdx.x, lane = tid & 31, wid = tid >> 5;
    const int mw = wid >> 2, nwc = wid & 3;      // warp grid 4x4
    const int m0 = mw * 16;                      // 16-row warp band
    const int n0 = nwc * 64;                     // N=256 layers
    const int n03 = nwc * 16;                    // N=64 layer
    const int nd = blockIdx.y;
    const int b0 = blockIdx.x * SM_M;
    const int rd = t & 1, wrp = rd ^ 1;
    const int p0 = c_par[nd][0], p1 = c_par[nd][1];

    float* sB1 = (float*)(sm + OFF_BIAS);
    float* sB2 = (float*)(sm + OFF_BIAS + 1024);
    float* sB3 = (float*)(sm + OFF_BIAS + 2048);
    if (tid < 256) { sB1[tid] = b1[nd*F0 + tid]; sB2[tid] = b2[nd*F0 + tid]; }
    if (tid < 64)  sB3[tid] = b3[nd*FML + tid];

    // per-thread ldmatrix base addresses
    const int rowoff = ((lane >> 3) & 1)*8 + (lane & 7);
    const int koffA  = (lane >> 4)*8;
    const uint32_t aH0 = smb + OFF_AH + (((uint32_t)(m0 + rowoff))*LDA + koffA)*2;
    const uint32_t aL0 = smb + OFF_AL + (((uint32_t)(m0 + rowoff))*LDA + koffA)*2;
    const uint32_t bRow = ((lane >> 3) & 1)*8 + (lane & 7);
    const uint32_t bCol = (uint32_t)(lane >> 4)*8;
    const uint32_t bOffL12 = (bRow*LDB + n0 + bCol)*2;
    const uint32_t bOffL3  = (bRow*LDB3 + n03 + bCol)*2;
    const uint32_t bufA[2] = { smb + OFF_B, smb + OFF_B + BUF_STRIDE };

    float acc[8][4];
#pragma unroll
    for (int b = 0; b < 8; b++)
#pragma unroll
        for (int c = 0; c < 4; c++) acc[b][c] = 0.f;

    // prefetch flat chunk 0
    prefetchFlat(nd, 0, bufA, tid);

    // gather L1 input A (fp16 split hi/lo): cols 0..159 (130..159 zero)
    {
        const float* Sp0 = &g_state2[rd][p0][0][0];
        const float* Sp1 = &g_state2[rd][p1][0][0];
        for (int i = tid; i < SM_M*K1; i += STHR) {
            int r = i / K1, c = i % K1;
            float v = 0.f;
            if (c < 2)        v = x[(size_t)(b0 + r)*(NNODE*T_TOT) + (c ? p1 : p0)*T_TOT + t];
            else if (c < 66)  v = Sp0[(size_t)(b0 + r)*FML + (c - 2)];
            else if (c < 130) v = Sp1[(size_t)(b0 + r)*FML + (c - 66)];
            __half h = __float2half_rn(v);
            *(__half*)(sm + OFF_AH + ((size_t)r*LDA + c)*2) = h;
            *(__half*)(sm + OFF_AL + ((size_t)r*LDA + c)*2) = __float2half_rn(v - __half2float(h));
        }
    }

    int fj = 0;
    // ===== LAYER 1: 5 k32 chunks, 2-pass (state precision) =====
    for (int kc = 0; kc < 5; kc++, fj++) {
        CP_WAIT0();
        __syncthreads();
        if (fj + 1 < NFLAT) prefetchFlat(nd, fj + 1, bufA, tid);
        uint32_t bb = bufA[fj & 1] + bOffL12;
        chunk256_2p(aH0 + kc*64,      aL0 + kc*64,      bb,        acc);
        chunk256_2p(aH0 + kc*64 + 32, aL0 + kc*64 + 32, bb + 8448, acc);
    }
    __syncthreads();
    epiA(acc, sB1, sm, m0, n0, lane);

    // ===== LAYER 2: 8 k32 chunks, 1-pass =====
    for (int kc = 0; kc < 8; kc++, fj++) {
        CP_WAIT0();
        __syncthreads();
        if (fj + 1 < NFLAT) prefetchFlat(nd, fj + 1, bufA, tid);
        uint32_t bb = bufA[fj & 1] + bOffL12;
        chunk256_1p(aH0 + kc*64,      bb,        acc);
        chunk256_1p(aH0 + kc*64 + 32, bb + 8448, acc);
    }
    __syncthreads();
    epiA(acc, sB2, sm, m0, n0, lane);

    // ===== LAYER 3: 4 k64 chunks, N=64, 1-pass =====
    for (int kc = 0; kc < 4; kc++, fj++) {
        CP_WAIT0();
        __syncthreads();
        if (fj + 1 < NFLAT) prefetchFlat(nd, fj + 1, bufA, tid);
        uint32_t bb = bufA[fj & 1] + bOffL3;
#pragma unroll
        for (int i = 0; i < 4; i++)
            chunk64_1p(aH0 + (4*kc + i)*32, bb + i*2304, acc);
    }

    // epilogue: state = tanh(acc + b3)
    float* gS = &g_state2[wrp][nd][0][0];
#pragma unroll
    for (int nf = 0; nf < 2; nf++) {
        int col = n03 + 8*nf + (lane & 3)*2;
        float bx = sB3[col], by = sB3[col+1];
        int r0 = m0 + (lane >> 2);
        float2 o0, o1;
        o0.x = tanhf(acc[nf][0] + bx);
        o0.y = tanhf(acc[nf][1] + by);
        o1.x = tanhf(acc[nf][2] + bx);
        o1.y = tanhf(acc[nf][3] + by);
        *(float2*)(gS + (size_t)(b0 + r0)*FML + col)     = o0;
        *(float2*)(gS + (size_t)(b0 + r0 + 8)*FML + col) = o1;
    }
}

// ---------------- final head (SIMT) ----------------
__device__ __forceinline__ void ldw256(const float* __restrict__ gW, int K, int kbase,
                                       int tid, float4* pre) {
#pragma unroll
    for (int p = 0; p < 4; p++) {
        int q = p*NTHR + tid, row = q >> 6, c4 = q & 63;
        float4 v = make_float4(0.f, 0.f, 0.f, 0.f);
        if (kbase + row < K) v = *(const float4*)(gW + (size_t)(kbase+row)*256 + c4*4);
        pre[p] = v;
    }
}
__device__ __forceinline__ void stw256(float* sW, int tid, const float4* pre) {
#pragma unroll
    for (int p = 0; p < 4; p++) {
        int q = p*NTHR + tid, row = q >> 6, c4 = q & 63;
        *(float4*)(sW + row*256 + c4*4) = pre[p];
    }
}
__device__ __forceinline__ void gemm256(const float* __restrict__ sA, int lda,
                                        const float* __restrict__ gW, int K,
                                        const float* __restrict__ gb,
                                        float* __restrict__ sOut, int ldo,
                                        float* sW, int tid)
{
    const int tm = tid >> 5, tn = tid & 31;
    const int m0 = tm * 8, n0 = tn * 2;
    ull acc[8][4];
#pragma unroll
    for (int i = 0; i < 8; i++)
#pragma unroll
        for (int j = 0; j < 4; j++) acc[i][j] = 0ull;
    const int nt = (K + KT - 1) / KT;
    float4 pre[4];
    ldw256(gW, K, 0, tid, pre);
    stw256(sW, tid, pre);
    __syncthreads();
    for (int kt = 0; kt < nt; kt++) {
        if (kt + 1 < nt) ldw256(gW, K, (kt+1)*KT, tid, pre);
        const float* Wb = sW + (kt & 1) * (KT*256);
        const float* Arow = sA + m0*lda + kt*KT;
#pragma unroll
        for (int kk = 0; kk < KT; kk++) {
            const ull* bp = (const ull*)(Wb + kk*256 + n0);
            ull w0 = bp[0], w1 = bp[32], w2 = bp[64], w3 = bp[96];
#pragma unroll
            for (int i = 0; i < 8; i++) {
                float a = Arow[i*lda + kk];
                ull aa = pack2(a, a);
                acc[i][0] = fma2(aa, w0, acc[i][0]);
                acc[i][1] = fma2(aa, w1, acc[i][1]);
                acc[i][2] = fma2(aa, w2, acc[i][2]);
                acc[i][3] = fma2(aa, w3, acc[i][3]);
            }
        }
        if (kt + 1 < nt) stw256(sW + ((kt+1) & 1)*(KT*256), tid, pre);
        __syncthreads();
    }
    float2 bb[4];
#pragma unroll
    for (int j = 0; j < 4; j++) bb[j] = *(const float2*)(gb + n0 + 64*j);
#pragma unroll
    for (int i = 0; i < 8; i++)
#pragma unroll
        for (int j = 0; j < 4; j++) {
            float2 v = unpack2(acc[i][j]);
            v.x = fmaxf(v.x + bb[j].x, 0.f);
            v.y = fmaxf(v.y + bb[j].y, 0.f);
            *(float2*)(sOut + (m0+i)*ldo + n0 + 64*j) = v;
        }
}

__global__ __launch_bounds__(NTHR) void final1_kernel(
    const float* __restrict__ x,
    const float* __restrict__ Wo1, const float* __restrict__ bo1)
{
    extern __shared__ float smem[];
    float* sF = smem;
    float* sW = sF + TILE_B*LDF;
    const int tid = threadIdx.x;
    const int b0  = blockIdx.x * TILE_B;
    const float* st = &g_state2[0][0][0][0];

    for (int i = tid; i < TILE_B*320; i += NTHR) {
        int m = i / 320, c = i % 320;
        sF[m*LDF + NNODE + c] = st[((size_t)(c >> 6)*B_TOT + (b0+m))*FML + (c & 63)];
    }
    for (int i = tid; i < TILE_B*NNODE; i += NTHR) {
        int m = i / NNODE, nn = i % NNODE;
        sF[m*LDF + nn] = x[(size_t)(b0+m)*(NNODE*T_TOT) + nn*T_TOT + (T_TOT-1)];
    }
    for (int i = tid; i < TILE_B*(LDF-KFEAT); i += NTHR) {
        int m = i / (LDF-KFEAT), c = KFEAT + i % (LDF-KFEAT);
        sF[m*LDF + c] = 0.f;
    }
    __syncthreads();
    gemm256(sF, LDF, Wo1, KFEAT, bo1, sF, LDF, sW, tid);
    __syncthreads();
    for (int i = tid; i < TILE_B*F0; i += NTHR) {
        int m = i >> 8, c = i & 255;
        g_h[(size_t)(b0+m)*F0 + c] = sF[m*LDF + c];
    }
    float s = 0.f, q = 0.f;
    for (int m = 0; m < TILE_B; m++) {
        float v = sF[m*LDF + tid];
        s += v; q += v*v;
    }
    g_psum[blockIdx.x*F0 + tid] = s;
    g_psq [blockIdx.x*F0 + tid] = q;
}

__global__ void bn_kernel(const float* __restrict__ gamma, const float* __restrict__ beta) {
    int c = threadIdx.x;
    float s = 0.f, q = 0.f;
    for (int b = 0; b < (B_TOT/TILE_B); b++) { s += g_psum[b*F0 + c]; q += g_psq[b*F0 + c]; }
    float mu  = s * (1.f / B_TOT);
    float var = q * (1.f / B_TOT) - mu * mu;
    float sc = gamma[c] * rsqrtf(var + 1e-5f);
    g_scale[c] = sc;
    g_shift[c] = beta[c] - mu * sc;
}

__global__ __launch_bounds__(NTHR) void final2_kernel(
    const float* __restrict__ Wo2, const float* __restrict__ bo2, float* __restrict__ out)
{
    __shared__ float sw2[F0*7], sb2[7], ssc[F0], ssh[F0];
    const int tid = threadIdx.x;
    for (int i = tid; i < F0*7; i += NTHR) sw2[i] = Wo2[i];
    if (tid < 7) sb2[tid] = bo2[tid];
    ssc[tid] = g_scale[tid];
    ssh[tid] = g_shift[tid];
    __syncthreads();
    const int warp = tid >> 5, lane = tid & 31;
    for (int r = 0; r < 16; r++) {
        int b = blockIdx.x*128 + warp*16 + r;
        float a0=0,a1=0,a2=0,a3=0,a4=0,a5=0,a6=0;
        const float* hp = g_h + (size_t)b*F0;
#pragma unroll
        for (int kk = 0; kk < 8; kk++) {
            int k = kk*32 + lane;
            float hv = hp[k]*ssc[k] + ssh[k];
            const float* wrp2 = sw2 + k*7;
            a0 += hv*wrp2[0]; a1 += hv*wrp2[1]; a2 += hv*wrp2[2]; a3 += hv*wrp2[3];
            a4 += hv*wrp2[4]; a5 += hv*wrp2[5]; a6 += hv*wrp2[6];
        }
#pragma unroll
        for (int off = 16; off; off >>= 1) {
            a0 += __shfl_down_sync(0xffffffffu, a0, off);
            a1 += __shfl_down_sync(0xffffffffu, a1, off);
            a2 += __shfl_down_sync(0xffffffffu, a2, off);
            a3 += __shfl_down_sync(0xffffffffu, a3, off);
            a4 += __shfl_down_sync(0xffffffffu, a4, off);
            a5 += __shfl_down_sync(0xffffffffu, a5, off);
            a6 += __shfl_down_sync(0xffffffffu, a6, off);
        }
        if (lane == 0) {
            float l[7] = { a0+sb2[0], a1+sb2[1], a2+sb2[2], a3+sb2[3], a4+sb2[4], a5+sb2[5], a6+sb2[6] };
            float mx = l[0];
#pragma unroll
            for (int j = 1; j < 7; j++) mx = fmaxf(mx, l[j]);
            float e[7], se = 0.f;
#pragma unroll
            for (int j = 0; j < 7; j++) { e[j] = expf(l[j] - mx); se += e[j]; }
            float inv = 1.f / se;
#pragma unroll
            for (int j = 0; j < 7; j++) out[(size_t)b*7 + j] = e[j]*inv;
        }
    }
}

__global__ void zero_state_kernel() {
    size_t n = (size_t)NNODE*B_TOT*FML;
    float* p = &g_state2[0][0][0][0];
    for (size_t i = blockIdx.x*(size_t)blockDim.x + threadIdx.x; i < n;
         i += (size_t)gridDim.x*blockDim.x) p[i] = 0.f;
}

extern "C" void kernel_launch(void* const* d_in, const int* in_sizes, int n_in,
                              void* d_out, int out_size)
{
    (void)in_sizes; (void)n_in; (void)out_size;
    const float* x     = (const float*)d_in[0];
    const float* W1    = (const float*)d_in[1];
    const float* b1    = (const float*)d_in[2];
    const float* W2    = (const float*)d_in[3];
    const float* b2    = (const float*)d_in[4];
    const float* W3    = (const float*)d_in[5];
    const float* b3    = (const float*)d_in[6];
    const float* Wo1   = (const float*)d_in[7];
    const float* bo1   = (const float*)d_in[8];
    const float* gamma = (const float*)d_in[9];
    const float* beta  = (const float*)d_in[10];
    const float* Wo2   = (const float*)d_in[11];
    const float* bo2   = (const float*)d_in[12];
    float* out = (float*)d_out;

    const int F1_SMEM = (TILE_B*LDF + 2*KT*256) * (int)sizeof(float);
    cudaFuncSetAttribute(step3_kernel,  cudaFuncAttributeMaxDynamicSharedMemorySize, STEP_SMEM);
    cudaFuncSetAttribute(final1_kernel, cudaFuncAttributeMaxDynamicSharedMemorySize, F1_SMEM);

    prep_kernel<<<512, 256>>>(W1, W2, W3);
    zero_state_kernel<<<512, 256>>>();

    dim3 sgrid(B_TOT/SM_M, NNODE);   // (128, 5) = 640 CTAs, 2 per SM
    for (int t = 0; t < T_TOT; t++)
        step3_kernel<<<sgrid, STHR, STEP_SMEM>>>(x, b1, b2, b3, t);

    final1_kernel<<<B_TOT/TILE_B, NTHR, F1_SMEM>>>(x, Wo1, bo1);
    bn_kernel<<<1, F0>>>(gamma, beta);
    final2_kernel<<<64, NTHR>>>(Wo2, bo2, out);
}